// round 2
// baseline (speedup 1.0000x reference)
#include <cuda_runtime.h>

// Problem constants (shapes are fixed by the dataset; E,N taken from in_sizes).
static constexpr float F_EPS = 1e-5f;
static constexpr float IS3   = 0.57735026918962576f;  // 1/sqrt(3)
static constexpr float PN    = 0.125f;                // 1/sqrt(2*MUL) = 1/8

// Scratch (no cudaMalloc allowed): per-node edge counts + BN statistics.
static __device__ float  g_cnt[10240];
static __device__ double g_stats[96];   // [0:32) sumS, [32:64) sumS2, [64:96) sumV2

// ---------------------------------------------------------------------------
// Shared-memory layout for the main kernel. edge_attr staging is dead after
// FC1, so it is unioned with the tensor-product coefficient arrays.
// ---------------------------------------------------------------------------
struct Coefs {
    float cA[32][32];      // PN * sh0 * x0[u]
    float cD[32][32];      // PN * IS3 * (x1[u] . sh1)
    float x0[32][32];      // raw x0[u]  (block B)
    float x1[32][32][3];   // raw x1[u][i] (block C)
};
union PrepSmem {
    float EA[32][128];     // edge_attr tile (FC1 input)
    Coefs c;
};

// One 32x4 (edges x cols) x K=128 GEMM micro-tile: acc[e][c] = b2 + Hs @ W2col
__device__ __forceinline__ void gemm_chunk(
    float (&acc)[4][4],
    const float (*Hs)[128], int e0,
    const float* __restrict__ Wp,     // = W2 + chunkCol + wc*4
    const float* __restrict__ b2p)    // = b2 + chunkCol + wc*4
{
    float4 bv = *reinterpret_cast<const float4*>(b2p);
    #pragma unroll
    for (int ii = 0; ii < 4; ++ii) {
        acc[ii][0] = bv.x; acc[ii][1] = bv.y; acc[ii][2] = bv.z; acc[ii][3] = bv.w;
    }
    #pragma unroll 2
    for (int k4 = 0; k4 < 128; k4 += 4) {
        float ha[4][4];
        #pragma unroll
        for (int ii = 0; ii < 4; ++ii)
            *reinterpret_cast<float4*>(ha[ii]) =
                *reinterpret_cast<const float4*>(&Hs[e0 + ii][k4]);
        #pragma unroll
        for (int kk = 0; kk < 4; ++kk) {
            float4 wv = *reinterpret_cast<const float4*>(Wp + (k4 + kk) * 4096);
            #pragma unroll
            for (int ii = 0; ii < 4; ++ii) {
                acc[ii][0] = fmaf(ha[ii][kk], wv.x, acc[ii][0]);
                acc[ii][1] = fmaf(ha[ii][kk], wv.y, acc[ii][1]);
                acc[ii][2] = fmaf(ha[ii][kk], wv.z, acc[ii][2]);
                acc[ii][3] = fmaf(ha[ii][kk], wv.w, acc[ii][3]);
            }
        }
    }
}

// ---------------------------------------------------------------------------
// Main fused kernel: FC1 -> FC2 (streamed) -> tensor product -> scatter-add
// One CTA = 32 edges, 256 threads. Thread (ec=tid>>5, wc=tid&31) owns a
// 4-edge x 4-col micro-tile; per 128-col chunk each thread holds one u.
// The 4 lanes {wc, wc^8, wc^16, wc^24} cover 4 different u for the same
// (e, w') output, reduced with shfl before the global atomic.
// ---------------------------------------------------------------------------
__global__ __launch_bounds__(256, 2)
void k_main(const float* __restrict__ node_attr,
            const int*   __restrict__ edge_index,
            const float* __restrict__ edge_attr,
            const float* __restrict__ edge_sh,
            const float* __restrict__ W1,
            const float* __restrict__ b1,
            const float* __restrict__ W2,
            const float* __restrict__ b2,
            float* __restrict__ outacc,
            int E)
{
    __shared__ PrepSmem sp;
    __shared__ float Hs[32][128];
    __shared__ float shBC[32][4];   // [0..2] = PN*IS3*sh1[i], [3] = PN*IS3*sh0
    __shared__ int   srcs[32];

    const int tid   = threadIdx.x;
    const int wc    = tid & 31;
    const int ec    = tid >> 5;
    const int e0    = ec * 4;
    const int ebase = blockIdx.x * 32;
    const int ug    = wc >> 3;      // which u within a 4-u group

    // ---- stage edge_attr tile ----
    #pragma unroll
    for (int it = 0; it < 4; ++it) {
        int idx = tid + it * 256;          // 1024 float4 slots
        int e = idx >> 5, q = idx & 31;
        int eg = ebase + e;
        float4 v = make_float4(0.f, 0.f, 0.f, 0.f);
        if (eg < E)
            v = *reinterpret_cast<const float4*>(edge_attr + (size_t)eg * 128 + q * 4);
        *reinterpret_cast<float4*>(&sp.EA[e][q * 4]) = v;
    }
    __syncthreads();

    // ---- FC1: Hs = relu(EA @ W1 + b1) ----
    {
        float acc[4][4];
        #pragma unroll
        for (int ii = 0; ii < 4; ++ii)
            acc[ii][0] = acc[ii][1] = acc[ii][2] = acc[ii][3] = 0.f;
        const float* W1p = W1 + wc * 4;
        #pragma unroll 2
        for (int k4 = 0; k4 < 128; k4 += 4) {
            float ha[4][4];
            #pragma unroll
            for (int ii = 0; ii < 4; ++ii)
                *reinterpret_cast<float4*>(ha[ii]) =
                    *reinterpret_cast<const float4*>(&sp.EA[e0 + ii][k4]);
            #pragma unroll
            for (int kk = 0; kk < 4; ++kk) {
                float4 wv = *reinterpret_cast<const float4*>(W1p + (k4 + kk) * 128);
                #pragma unroll
                for (int ii = 0; ii < 4; ++ii) {
                    acc[ii][0] = fmaf(ha[ii][kk], wv.x, acc[ii][0]);
                    acc[ii][1] = fmaf(ha[ii][kk], wv.y, acc[ii][1]);
                    acc[ii][2] = fmaf(ha[ii][kk], wv.z, acc[ii][2]);
                    acc[ii][3] = fmaf(ha[ii][kk], wv.w, acc[ii][3]);
                }
            }
        }
        float b1a[4];
        *reinterpret_cast<float4*>(b1a) =
            *reinterpret_cast<const float4*>(b1 + wc * 4);
        #pragma unroll
        for (int ii = 0; ii < 4; ++ii)
            #pragma unroll
            for (int cc = 0; cc < 4; ++cc)
                Hs[e0 + ii][wc * 4 + cc] = fmaxf(acc[ii][cc] + b1a[cc], 0.f);
    }
    __syncthreads();   // FC1 done: EA region may now be overwritten by coefs

    // ---- per-edge tensor-product coefficients (8 threads / edge) ----
    {
        int e = tid >> 3, j = tid & 7;
        int eg = ebase + e;
        if (eg < E) {
            float4 shv = *reinterpret_cast<const float4*>(edge_sh + (size_t)eg * 4);
            if (j == 0) {
                int src = edge_index[eg];
                srcs[e] = src;
                shBC[e][0] = PN * IS3 * shv.y;
                shBC[e][1] = PN * IS3 * shv.z;
                shBC[e][2] = PN * IS3 * shv.w;
                shBC[e][3] = PN * IS3 * shv.x;
                atomicAdd(&g_cnt[src], 1.0f);
            }
            int dst = edge_index[E + eg];
            const float* xr = node_attr + (size_t)dst * 128;
            float x0a[4];
            *reinterpret_cast<float4*>(x0a) =
                *reinterpret_cast<const float4*>(xr + j * 4);
            float x1a[12];
            #pragma unroll
            for (int t = 0; t < 6; ++t)
                *reinterpret_cast<float2*>(&x1a[t * 2]) =
                    *reinterpret_cast<const float2*>(xr + 32 + j * 12 + t * 2);
            #pragma unroll
            for (int t = 0; t < 4; ++t) {
                int u = j * 4 + t;
                sp.c.x0[e][u] = x0a[t];
                sp.c.cA[e][u] = PN * shv.x * x0a[t];
                float d = x1a[3*t] * shv.y + x1a[3*t+1] * shv.z + x1a[3*t+2] * shv.w;
                sp.c.cD[e][u] = PN * IS3 * d;
                sp.c.x1[e][u][0] = x1a[3*t];
                sp.c.x1[e][u][1] = x1a[3*t+1];
                sp.c.x1[e][u][2] = x1a[3*t+2];
            }
        } else {
            if (j == 0) {
                srcs[e] = 0;
                shBC[e][0] = shBC[e][1] = shBC[e][2] = shBC[e][3] = 0.f;
            }
            #pragma unroll
            for (int t = 0; t < 4; ++t) {
                int u = j * 4 + t;
                sp.c.x0[e][u] = 0.f; sp.c.cA[e][u] = 0.f; sp.c.cD[e][u] = 0.f;
                sp.c.x1[e][u][0] = sp.c.x1[e][u][1] = sp.c.x1[e][u][2] = 0.f;
            }
        }
    }
    __syncthreads();

    // ================= Phase A + D : scalar output out0 =================
    float out0[4][4];
    #pragma unroll
    for (int ii = 0; ii < 4; ++ii)
        out0[ii][0] = out0[ii][1] = out0[ii][2] = out0[ii][3] = 0.f;

    #pragma unroll 1
    for (int cb = 0; cb < 16; ++cb) {
        int ci = cb & 7;
        int xoff = (cb < 8) ? 0 : 3072;           // block A then block D
        int u = ci * 4 + ug;
        const float* Wp = W2 + xoff + ci * 128 + wc * 4;
        const float* bp = b2 + xoff + ci * 128 + wc * 4;
        float acc[4][4];
        gemm_chunk(acc, Hs, e0, Wp, bp);
        #pragma unroll
        for (int ii = 0; ii < 4; ++ii) {
            float coef = (cb < 8) ? sp.c.cA[e0 + ii][u] : sp.c.cD[e0 + ii][u];
            #pragma unroll
            for (int cc = 0; cc < 4; ++cc)
                out0[ii][cc] = fmaf(coef, acc[ii][cc], out0[ii][cc]);
        }
    }
    #pragma unroll
    for (int ii = 0; ii < 4; ++ii)
        #pragma unroll
        for (int cc = 0; cc < 4; ++cc) {
            float v = out0[ii][cc];
            v += __shfl_xor_sync(0xffffffffu, v, 8);
            v += __shfl_xor_sync(0xffffffffu, v, 16);
            out0[ii][cc] = v;
        }
    if (wc < 8) {
        #pragma unroll
        for (int ii = 0; ii < 4; ++ii) {
            float* op = outacc + (size_t)srcs[e0 + ii] * 128 + wc * 4;
            #pragma unroll
            for (int cc = 0; cc < 4; ++cc)
                atomicAdd(op + cc, out0[ii][cc]);
        }
    }

    // ================= Phase B : tB[w] = sum_u x0[u]*wB[u,w] =================
    float tB[4][4];
    #pragma unroll
    for (int ii = 0; ii < 4; ++ii)
        tB[ii][0] = tB[ii][1] = tB[ii][2] = tB[ii][3] = 0.f;

    #pragma unroll 1
    for (int ci = 0; ci < 8; ++ci) {
        int u = ci * 4 + ug;
        const float* Wp = W2 + 1024 + ci * 128 + wc * 4;
        const float* bp = b2 + 1024 + ci * 128 + wc * 4;
        float acc[4][4];
        gemm_chunk(acc, Hs, e0, Wp, bp);
        #pragma unroll
        for (int ii = 0; ii < 4; ++ii) {
            float coef = sp.c.x0[e0 + ii][u];
            #pragma unroll
            for (int cc = 0; cc < 4; ++cc)
                tB[ii][cc] = fmaf(coef, acc[ii][cc], tB[ii][cc]);
        }
    }

    // ============ Phase C : vC[w][i] = sum_u x1[u][i]*wC[u,w] ============
    float vC[4][4][3];
    #pragma unroll
    for (int ii = 0; ii < 4; ++ii)
        #pragma unroll
        for (int cc = 0; cc < 4; ++cc)
            vC[ii][cc][0] = vC[ii][cc][1] = vC[ii][cc][2] = 0.f;

    #pragma unroll 1
    for (int ci = 0; ci < 8; ++ci) {
        int u = ci * 4 + ug;
        const float* Wp = W2 + 2048 + ci * 128 + wc * 4;
        const float* bp = b2 + 2048 + ci * 128 + wc * 4;
        float acc[4][4];
        gemm_chunk(acc, Hs, e0, Wp, bp);
        #pragma unroll
        for (int ii = 0; ii < 4; ++ii) {
            float c0 = sp.c.x1[e0 + ii][u][0];
            float c1 = sp.c.x1[e0 + ii][u][1];
            float c2 = sp.c.x1[e0 + ii][u][2];
            #pragma unroll
            for (int cc = 0; cc < 4; ++cc) {
                vC[ii][cc][0] = fmaf(c0, acc[ii][cc], vC[ii][cc][0]);
                vC[ii][cc][1] = fmaf(c1, acc[ii][cc], vC[ii][cc][1]);
                vC[ii][cc][2] = fmaf(c2, acc[ii][cc], vC[ii][cc][2]);
            }
        }
    }

    // ---- reduce over u-lane groups, combine B+C, scatter out1 ----
    #pragma unroll
    for (int ii = 0; ii < 4; ++ii)
        #pragma unroll
        for (int cc = 0; cc < 4; ++cc) {
            float v = tB[ii][cc];
            v += __shfl_xor_sync(0xffffffffu, v, 8);
            v += __shfl_xor_sync(0xffffffffu, v, 16);
            tB[ii][cc] = v;
            #pragma unroll
            for (int i3 = 0; i3 < 3; ++i3) {
                float w = vC[ii][cc][i3];
                w += __shfl_xor_sync(0xffffffffu, w, 8);
                w += __shfl_xor_sync(0xffffffffu, w, 16);
                vC[ii][cc][i3] = w;
            }
        }
    if (wc < 8) {
        #pragma unroll
        for (int ii = 0; ii < 4; ++ii) {
            int e = e0 + ii;
            float sb0 = shBC[e][0], sb1 = shBC[e][1], sb2 = shBC[e][2];
            float sc  = shBC[e][3];
            float* op = outacc + (size_t)srcs[e] * 128 + 32 + wc * 12;
            #pragma unroll
            for (int cc = 0; cc < 4; ++cc) {
                float t = tB[ii][cc];
                atomicAdd(op + cc * 3 + 0, fmaf(sb0, t, sc * vC[ii][cc][0]));
                atomicAdd(op + cc * 3 + 1, fmaf(sb1, t, sc * vC[ii][cc][1]));
                atomicAdd(op + cc * 3 + 2, fmaf(sb2, t, sc * vC[ii][cc][2]));
            }
        }
    }
}

// ---------------------------------------------------------------------------
// Zero accumulators (out is also the segment-sum accumulator).
// ---------------------------------------------------------------------------
__global__ void k_zero(float* __restrict__ outp, int n_out, int N)
{
    int i = blockIdx.x * blockDim.x + threadIdx.x;
    int stride = gridDim.x * blockDim.x;
    for (int t = i; t < n_out; t += stride) outp[t] = 0.f;
    for (int t = i; t < N;     t += stride) g_cnt[t] = 0.f;
    for (int t = i; t < 96;    t += stride) g_stats[t] = 0.0;
}

// ---------------------------------------------------------------------------
// Mean over incoming edges + residual, and BN statistics (double accumulation).
// 256 threads = 32 rows x 8 threads; writes the pre-BN value back to out.
// ---------------------------------------------------------------------------
__global__ __launch_bounds__(256)
void k_stats(float* __restrict__ outp, const float* __restrict__ node_attr, int N)
{
    __shared__ float sS[32], sS2[32], sV2[32];
    int tid = threadIdx.x;
    if (tid < 32) { sS[tid] = 0.f; sS2[tid] = 0.f; sV2[tid] = 0.f; }
    __syncthreads();

    int r = blockIdx.x * 32 + (tid >> 3);
    int j = tid & 7;
    if (r < N) {
        float inv = 1.0f / fmaxf(g_cnt[r], 1.0f);
        size_t base = (size_t)r * 128 + j * 16;
        float v[16];
        #pragma unroll
        for (int t = 0; t < 4; ++t) {
            float4 a = *reinterpret_cast<const float4*>(outp + base + t * 4);
            float4 b = *reinterpret_cast<const float4*>(node_attr + base + t * 4);
            v[t*4+0] = fmaf(a.x, inv, b.x);
            v[t*4+1] = fmaf(a.y, inv, b.y);
            v[t*4+2] = fmaf(a.z, inv, b.z);
            v[t*4+3] = fmaf(a.w, inv, b.w);
            float4 w = make_float4(v[t*4+0], v[t*4+1], v[t*4+2], v[t*4+3]);
            *reinterpret_cast<float4*>(outp + base + t * 4) = w;
        }
        if (j < 2) {
            #pragma unroll
            for (int t = 0; t < 16; ++t) {
                int c = j * 16 + t;
                atomicAdd(&sS[c],  v[t]);
                atomicAdd(&sS2[c], v[t] * v[t]);
            }
        } else {
            #pragma unroll
            for (int t = 0; t < 16; ++t) {
                int c = j * 16 + t;
                atomicAdd(&sV2[(c - 32) / 3], v[t] * v[t]);
            }
        }
    }
    __syncthreads();
    if (tid < 32) {
        atomicAdd(&g_stats[tid],      (double)sS[tid]);
        atomicAdd(&g_stats[32 + tid], (double)sS2[tid]);
        atomicAdd(&g_stats[64 + tid], (double)sV2[tid]);
    }
}

// ---------------------------------------------------------------------------
// Finalize BN: per-channel scale/shift computed once per CTA, then applied.
// ---------------------------------------------------------------------------
__global__ void k_apply(float* __restrict__ outp,
                        const float* __restrict__ bnw,
                        const float* __restrict__ bnb,
                        int N, int total)
{
    __shared__ float pAll[128], qAll[128];
    int tid = threadIdx.x;
    if (tid < 128) {
        float p, q = 0.f;
        if (tid < 32) {
            double meanS = g_stats[tid] / N;
            double var   = g_stats[32 + tid] / N - meanS * meanS;
            p = rsqrtf((float)var + F_EPS) * bnw[tid];
            q = bnb[tid] - (float)meanS * p;
        } else {
            int u = (tid - 32) / 3;
            double mv = g_stats[64 + u] / (3.0 * N);
            p = rsqrtf((float)mv + F_EPS) * bnw[32 + u];
        }
        pAll[tid] = p; qAll[tid] = q;
    }
    __syncthreads();
    int stride = gridDim.x * blockDim.x;
    for (int i = blockIdx.x * blockDim.x + tid; i < total; i += stride) {
        int c = i & 127;
        outp[i] = fmaf(outp[i], pAll[c], qAll[c]);
    }
}

// ---------------------------------------------------------------------------
extern "C" void kernel_launch(void* const* d_in, const int* in_sizes, int n_in,
                              void* d_out, int out_size)
{
    const float* node_attr  = (const float*)d_in[0];
    const int*   edge_index = (const int*)  d_in[1];
    const float* edge_attr  = (const float*)d_in[2];
    const float* edge_sh    = (const float*)d_in[3];
    const float* W1         = (const float*)d_in[4];
    const float* b1         = (const float*)d_in[5];
    const float* W2         = (const float*)d_in[6];
    const float* b2         = (const float*)d_in[7];
    const float* bnw        = (const float*)d_in[8];
    const float* bnb        = (const float*)d_in[9];
    float* outp = (float*)d_out;

    const int N = in_sizes[0] / 128;
    const int E = in_sizes[2] / 128;

    k_zero <<<256, 256>>>(outp, out_size, N);
    k_main <<<(E + 31) / 32, 256>>>(node_attr, edge_index, edge_attr, edge_sh,
                                    W1, b1, W2, b2, outp, E);
    k_stats<<<(N + 31) / 32, 256>>>(outp, node_attr, N);
    k_apply<<<512, 256>>>(outp, bnw, bnb, N, out_size);
}

// round 7
// speedup vs baseline: 2.6411x; 2.6411x over previous
#include <cuda_runtime.h>
#include <cuda_bf16.h>
#include <cstdint>

// ============================ problem constants ============================
static constexpr float F_EPS = 1e-5f;
static constexpr float PN    = 0.125f;                        // 1/sqrt(2*32)
static constexpr float PIS3  = 0.125f * 0.57735026918962576f; // PN/sqrt(3)

// ============================ device scratch ===============================
static __device__ float  g_cnt[10240];
static __device__ double g_stats[96];
// Padded (272B-row) bf16 hi/lo weight images, cp.async-staged verbatim:
//  W1T: 128 rows(n) x 128(k): hi [0,34816) | lo [34816,69632)
static __device__ __align__(128) unsigned char g_W1T[69632];
//  W2T: 64 chunks; chunk = 64 rows(n) x 128(k): hi 17408 | lo 17408
static __device__ __align__(128) unsigned char g_W2T[64 * 34816];

// ============================ smem layout ==================================
static constexpr uint32_t H_HI = 0;        // 34816: EA/H hi tile (272B rows)
static constexpr uint32_t H_LO = 34816;    // 34816: EA/H lo tile
static constexpr uint32_t XR   = 69632;    // 65536: X transposed [j][e] fp32
static constexpr uint32_t BUF0 = 135168;   // 34816: W2 chunk ring (also W1T hi)
static constexpr uint32_t BUF1 = 169984;   // 34816: (also W1T lo)
static constexpr uint32_t COEF = 204800;   // 2560 f32 coefs + 512 srcs
static constexpr uint32_t SMEM_SZ = 207872;

// ============================ PTX helpers ==================================
__device__ __forceinline__ uint32_t smem_u32(const void* p) {
    uint32_t a;
    asm("{ .reg .u64 t; cvta.to.shared.u64 t, %1; cvt.u32.u64 %0, t; }" : "=r"(a) : "l"(p));
    return a;
}
__device__ __forceinline__ void ldsm_x4(uint32_t (&r)[4], uint32_t a) {
    asm volatile("ldmatrix.sync.aligned.m8n8.x4.shared.b16 {%0,%1,%2,%3}, [%4];"
        : "=r"(r[0]), "=r"(r[1]), "=r"(r[2]), "=r"(r[3]) : "r"(a));
}
__device__ __forceinline__ void mma_bf16(float (&d)[4], const uint32_t (&a)[4],
                                         uint32_t b0, uint32_t b1) {
    asm volatile(
        "mma.sync.aligned.m16n8k16.row.col.f32.bf16.bf16.f32 "
        "{%0,%1,%2,%3}, {%4,%5,%6,%7}, {%8,%9}, {%0,%1,%2,%3};"
        : "+f"(d[0]), "+f"(d[1]), "+f"(d[2]), "+f"(d[3])
        : "r"(a[0]), "r"(a[1]), "r"(a[2]), "r"(a[3]), "r"(b0), "r"(b1));
}
__device__ __forceinline__ void cp16(uint32_t s, const void* g) {
    asm volatile("cp.async.cg.shared.global [%0], [%1], 16;" :: "r"(s), "l"(g));
}
#define CP_COMMIT() asm volatile("cp.async.commit_group;" ::: "memory")
#define CP_WAIT(n)  asm volatile("cp.async.wait_group %0;" :: "n"(n) : "memory")

// ldmatrix lane->address maps (272B row stride):
// A-operand x4 (m16k16): M0 rows g0-7 k0 | M1 rows g8-15 k0 | M2 g0-7 k8 | M3 g8-15 k8
__device__ __forceinline__ uint32_t ldsm_addr_A(uint32_t base, int row0, int lane) {
    return base + (uint32_t)(row0 + ((lane >> 3) & 1) * 8 + (lane & 7)) * 272u
                + (uint32_t)(lane >> 4) * 16u;
}
// B-operand x4 (2x k16n8): M0 n0-7 k0 | M1 n0-7 k8 | M2 n8-15 k0 | M3 n8-15 k8
__device__ __forceinline__ uint32_t ldsm_addr_B(uint32_t base, int n0, int lane) {
    return base + (uint32_t)(n0 + (lane >> 4) * 8 + (lane & 7)) * 272u
                + (uint32_t)((lane >> 3) & 1) * 16u;
}

__device__ __forceinline__ uint32_t pack_bf2(float a, float b) {
    __nv_bfloat162 t = __floats2bfloat162_rn(a, b);
    return *reinterpret_cast<uint32_t*>(&t);
}
__device__ __forceinline__ float bf_hi(float a) {
    return __bfloat162float(__float2bfloat16_rn(a));
}

// ============================ prep kernels =================================
__global__ void k_prep_w1(const float* __restrict__ W1)
{
    int idx = blockIdx.x * blockDim.x + threadIdx.x;   // k*128 + n (n inner: coalesced reads)
    if (idx >= 128 * 128) return;
    int n = idx & 127, k = idx >> 7;
    float v  = W1[k * 128 + n];                        // B'[n][k] = W1[k][n]
    float hi = bf_hi(v);
    uint32_t off = (uint32_t)n * 272u + (uint32_t)k * 2u;
    *reinterpret_cast<__nv_bfloat16*>(g_W1T + off)         = __float2bfloat16_rn(hi);
    *reinterpret_cast<__nv_bfloat16*>(g_W1T + 34816 + off) = __float2bfloat16_rn(v - hi);
}

__global__ void k_prep_w2(const float* __restrict__ W2)
{
    int idx = blockIdx.x * blockDim.x + threadIdx.x;   // c*8192 + k*64 + n
    if (idx >= 64 * 128 * 64) return;
    int n = idx & 63, k = (idx >> 6) & 127, c = idx >> 13;
    int bt = c >> 4;
    int bb = (bt == 0) ? 0 : (bt == 1) ? 3072 : (bt == 2) ? 1024 : 2048;  // A,D,B,C
    int u  = 2 * (c & 15) + (n >> 5);
    int col = bb + u * 32 + (n & 31);
    float v  = W2[k * 4096 + col];                     // B'[n][k] = W2[k][col]
    float hi = bf_hi(v);
    unsigned char* base = g_W2T + (size_t)c * 34816;
    uint32_t off = (uint32_t)n * 272u + (uint32_t)k * 2u;
    *reinterpret_cast<__nv_bfloat16*>(base + off)         = __float2bfloat16_rn(hi);
    *reinterpret_cast<__nv_bfloat16*>(base + 17408 + off) = __float2bfloat16_rn(v - hi);
}

// ============================ main kernel ==================================
__global__ __launch_bounds__(256, 1)
void k_main(const float* __restrict__ node_attr,
            const int*   __restrict__ edge_index,
            const float* __restrict__ edge_attr,
            const float* __restrict__ edge_sh,
            const float* __restrict__ b1g,
            const float* __restrict__ b2g,
            float* __restrict__ outacc,
            int E)
{
    extern __shared__ unsigned char smem[];
    const uint32_t sb = smem_u32(smem);
    const int tid  = threadIdx.x;
    const int lane = tid & 31;
    const int w    = tid >> 5;
    const int ebase = blockIdx.x * 128;

    // ---- stage W1T (69632B) into BUF0..BUF1 via cp.async ----
    {
        #pragma unroll 1
        for (int off = tid * 16; off < 69632; off += 4096)
            cp16(sb + BUF0 + off, g_W1T + off);
        CP_COMMIT();
    }

    // ---- stage EA (bf16 hi/lo, padded), X (transposed), per-edge coefs ----
    {
        int e = tid >> 1, h = tid & 1, eg = ebase + e;
        float* X   = (float*)(smem + XR);
        float* A0s = (float*)(smem + COEF);      // PN*sh0
        float* D1s = A0s + 128;                  // PIS3*sh1x | +128 y | +256 z
        float* P0s = A0s + 512;                  // PIS3*sh0
        int*   SR  = (int*)(smem + COEF + 2560);
        if (eg < E) {
            const float4* ea = (const float4*)(edge_attr + (size_t)eg * 128 + h * 64);
            #pragma unroll
            for (int q = 0; q < 16; ++q) {
                float4 v = __ldg(ea + q);
                int jc = h * 64 + q * 4;
                float h0 = bf_hi(v.x), h1 = bf_hi(v.y), h2 = bf_hi(v.z), h3 = bf_hi(v.w);
                uint32_t off = (uint32_t)e * 272u + (uint32_t)jc * 2u;
                *(uint32_t*)(smem + H_HI + off)     = pack_bf2(h0, h1);
                *(uint32_t*)(smem + H_HI + off + 4) = pack_bf2(h2, h3);
                *(uint32_t*)(smem + H_LO + off)     = pack_bf2(v.x - h0, v.y - h1);
                *(uint32_t*)(smem + H_LO + off + 4) = pack_bf2(v.z - h2, v.w - h3);
            }
            int dst = __ldg(edge_index + E + eg);
            const float4* xr = (const float4*)(node_attr + (size_t)dst * 128 + h * 64);
            #pragma unroll
            for (int q = 0; q < 16; ++q) {
                float4 v = __ldg(xr + q);
                int jr = h * 64 + q * 4;
                X[(jr + 0) * 128 + e] = v.x;  X[(jr + 1) * 128 + e] = v.y;
                X[(jr + 2) * 128 + e] = v.z;  X[(jr + 3) * 128 + e] = v.w;
            }
            if (h == 0) {
                int src = __ldg(edge_index + eg);
                float4 shv = __ldg((const float4*)(edge_sh + (size_t)eg * 4));
                A0s[e] = PN * shv.x;
                D1s[e] = PIS3 * shv.y; D1s[128 + e] = PIS3 * shv.z; D1s[256 + e] = PIS3 * shv.w;
                P0s[e] = PIS3 * shv.x;
                SR[e]  = src;
                atomicAdd(&g_cnt[src], 1.0f);
            }
        } else {
            #pragma unroll
            for (int q = 0; q < 16; ++q) {
                int jc = h * 64 + q * 4;
                uint32_t off = (uint32_t)e * 272u + (uint32_t)jc * 2u;
                *(uint32_t*)(smem + H_HI + off)     = 0u;
                *(uint32_t*)(smem + H_HI + off + 4) = 0u;
                *(uint32_t*)(smem + H_LO + off)     = 0u;
                *(uint32_t*)(smem + H_LO + off + 4) = 0u;
                X[(jc + 0) * 128 + e] = 0.f;  X[(jc + 1) * 128 + e] = 0.f;
                X[(jc + 2) * 128 + e] = 0.f;  X[(jc + 3) * 128 + e] = 0.f;
            }
            if (h == 0) {
                A0s[e] = 0.f; D1s[e] = 0.f; D1s[128 + e] = 0.f; D1s[256 + e] = 0.f;
                P0s[e] = 0.f; SR[e] = 0;
            }
        }
    }
    CP_WAIT(0);
    __syncthreads();                                   // (#1)

    const int g = lane >> 2, j = lane & 3;

    // =========================== FC1 (bf16x3 HMMA) ==========================
    {
        float acc1[16][4];
        #pragma unroll
        for (int t = 0; t < 16; ++t)
            acc1[t][0] = acc1[t][1] = acc1[t][2] = acc1[t][3] = 0.f;
        const uint32_t aH = ldsm_addr_A(sb + H_HI, 16 * w, lane);
        const uint32_t aL = ldsm_addr_A(sb + H_LO, 16 * w, lane);
        #pragma unroll 2
        for (int k = 0; k < 8; ++k) {
            uint32_t Ah[4], Al[4];
            ldsm_x4(Ah, aH + k * 32);
            ldsm_x4(Al, aL + k * 32);
            #pragma unroll
            for (int p = 0; p < 8; ++p) {
                uint32_t Bh[4], Bl[4];
                ldsm_x4(Bh, ldsm_addr_B(sb + BUF0,         16 * p, lane) + k * 32);
                ldsm_x4(Bl, ldsm_addr_B(sb + BUF0 + 34816, 16 * p, lane) + k * 32);
                mma_bf16(acc1[2*p],   Ah, Bh[0], Bh[1]);
                mma_bf16(acc1[2*p],   Ah, Bl[0], Bl[1]);
                mma_bf16(acc1[2*p],   Al, Bh[0], Bh[1]);
                mma_bf16(acc1[2*p+1], Ah, Bh[2], Bh[3]);
                mma_bf16(acc1[2*p+1], Ah, Bl[2], Bl[3]);
                mma_bf16(acc1[2*p+1], Al, Bh[2], Bh[3]);
            }
        }
        // epilogue: h = relu(D + b1), split hi/lo, write back into H tile
        int r0 = 16 * w + g, r1 = r0 + 8;
        #pragma unroll
        for (int t = 0; t < 16; ++t) {
            int c0 = 8 * t + 2 * j;
            float b1a = __ldg(b1g + c0), b1b = __ldg(b1g + c0 + 1);
            float a0 = fmaxf(acc1[t][0] + b1a, 0.f), a1 = fmaxf(acc1[t][1] + b1b, 0.f);
            float a2 = fmaxf(acc1[t][2] + b1a, 0.f), a3 = fmaxf(acc1[t][3] + b1b, 0.f);
            float h0 = bf_hi(a0), h1 = bf_hi(a1), h2 = bf_hi(a2), h3 = bf_hi(a3);
            uint32_t o0 = (uint32_t)r0 * 272u + (uint32_t)c0 * 2u;
            uint32_t o1 = (uint32_t)r1 * 272u + (uint32_t)c0 * 2u;
            *(uint32_t*)(smem + H_HI + o0) = pack_bf2(h0, h1);
            *(uint32_t*)(smem + H_LO + o0) = pack_bf2(a0 - h0, a1 - h1);
            *(uint32_t*)(smem + H_HI + o1) = pack_bf2(h2, h3);
            *(uint32_t*)(smem + H_LO + o1) = pack_bf2(a2 - h2, a3 - h3);
        }
    }
    __syncthreads();                                   // (#2) W1T buffers free

    // prefetch FC2 chunks 0 and 1
    {
        #pragma unroll 1
        for (int off = tid * 16; off < 34816; off += 4096)
            cp16(sb + BUF0 + off, g_W2T + off);
        CP_COMMIT();
        #pragma unroll 1
        for (int off = tid * 16; off < 34816; off += 4096)
            cp16(sb + BUF1 + off, g_W2T + 34816 + off);
        CP_COMMIT();
    }

    // =========================== FC2 + contraction ==========================
    const float* X   = (const float*)(smem + XR);
    const float* A0s = (const float*)(smem + COEF);
    const float* D1s = A0s + 128;
    const float* P0s = A0s + 512;
    const int*   SR  = (const int*)(smem + COEF + 2560);
    const int e0 = 16 * w + g, e1 = e0 + 8;
    const uint32_t aH = ldsm_addr_A(sb + H_HI, 16 * w, lane);
    const uint32_t aL = ldsm_addr_A(sb + H_LO, 16 * w, lane);

    float accS[2][8];                      // blocks A+D -> out0, then block B -> tB
    float vC[3][2][8];                     // block C
    #pragma unroll
    for (int i = 0; i < 8; ++i) { accS[0][i] = 0.f; accS[1][i] = 0.f; }

    #pragma unroll 1
    for (int c = 0; c < 64; ++c) {
        CP_WAIT(1);
        __syncthreads();                               // chunk c visible, buffers settled
        const uint32_t bufB = sb + ((c & 1) ? BUF1 : BUF0);

        float acc[8][4];
        #pragma unroll
        for (int t = 0; t < 8; ++t)
            acc[t][0] = acc[t][1] = acc[t][2] = acc[t][3] = 0.f;

        #pragma unroll 2
        for (int k = 0; k < 8; ++k) {
            uint32_t Ah[4], Al[4];
            ldsm_x4(Ah, aH + k * 32);
            ldsm_x4(Al, aL + k * 32);
            #pragma unroll
            for (int p = 0; p < 4; ++p) {
                uint32_t Bh[4], Bl[4];
                ldsm_x4(Bh, ldsm_addr_B(bufB,         16 * p, lane) + k * 32);
                ldsm_x4(Bl, ldsm_addr_B(bufB + 17408, 16 * p, lane) + k * 32);
                mma_bf16(acc[2*p],   Ah, Bh[0], Bh[1]);
                mma_bf16(acc[2*p],   Ah, Bl[0], Bl[1]);
                mma_bf16(acc[2*p],   Al, Bh[0], Bh[1]);
                mma_bf16(acc[2*p+1], Ah, Bh[2], Bh[3]);
                mma_bf16(acc[2*p+1], Ah, Bl[2], Bl[3]);
                mma_bf16(acc[2*p+1], Al, Bh[2], Bh[3]);
            }
        }

        // ---- contraction of this chunk's D fragments ----
        const int cw = c & 15, bt = c >> 4;
        const int bb = (bt == 0) ? 0 : (bt == 1) ? 3072 : (bt == 2) ? 1024 : 2048;
        if (c == 48) {
            #pragma unroll
            for (int i = 0; i < 8; ++i) {
                vC[0][0][i] = 0.f; vC[0][1][i] = 0.f;
                vC[1][0][i] = 0.f; vC[1][1][i] = 0.f;
                vC[2][0][i] = 0.f; vC[2][1][i] = 0.f;
            }
        }
        #pragma unroll
        for (int hh = 0; hh < 2; ++hh) {
            const int u = 2 * cw + hh;
            if (bt == 3) {
                float cx0 = X[(32+3*u)*128+e0], cy0 = X[(33+3*u)*128+e0], cz0 = X[(34+3*u)*128+e0];
                float cx1 = X[(32+3*u)*128+e1], cy1 = X[(33+3*u)*128+e1], cz1 = X[(34+3*u)*128+e1];
                #pragma unroll
                for (int t4 = 0; t4 < 4; ++t4) {
                    int t = hh * 4 + t4, wp = 8 * t4 + 2 * j;
                    float b2a = __ldg(b2g + bb + u * 32 + wp);
                    float b2b = __ldg(b2g + bb + u * 32 + wp + 1);
                    float y0 = acc[t][0] + b2a, y1 = acc[t][1] + b2b;
                    float y2 = acc[t][2] + b2a, y3 = acc[t][3] + b2b;
                    int i0 = 2 * t4, i1 = i0 + 1;
                    vC[0][0][i0] = fmaf(cx0, y0, vC[0][0][i0]); vC[0][0][i1] = fmaf(cx0, y1, vC[0][0][i1]);
                    vC[1][0][i0] = fmaf(cy0, y0, vC[1][0][i0]); vC[1][0][i1] = fmaf(cy0, y1, vC[1][0][i1]);
                    vC[2][0][i0] = fmaf(cz0, y0, vC[2][0][i0]); vC[2][0][i1] = fmaf(cz0, y1, vC[2][0][i1]);
                    vC[0][1][i0] = fmaf(cx1, y2, vC[0][1][i0]); vC[0][1][i1] = fmaf(cx1, y3, vC[0][1][i1]);
                    vC[1][1][i0] = fmaf(cy1, y2, vC[1][1][i0]); vC[1][1][i1] = fmaf(cy1, y3, vC[1][1][i1]);
                    vC[2][1][i0] = fmaf(cz1, y2, vC[2][1][i0]); vC[2][1][i1] = fmaf(cz1, y3, vC[2][1][i1]);
                }
            } else {
                float c0, c1;
                if (bt == 0) {
                    c0 = A0s[e0] * X[u*128+e0];
                    c1 = A0s[e1] * X[u*128+e1];
                } else if (bt == 1) {
                    c0 = D1s[e0]     * X[(32+3*u)*128+e0]
                       + D1s[128+e0] * X[(33+3*u)*128+e0]
                       + D1s[256+e0] * X[(34+3*u)*128+e0];
                    c1 = D1s[e1]     * X[(32+3*u)*128+e1]
                       + D1s[128+e1] * X[(33+3*u)*128+e1]
                       + D1s[256+e1] * X[(34+3*u)*128+e1];
                } else {
                    c0 = X[u*128+e0];
                    c1 = X[u*128+e1];
                }
                #pragma unroll
                for (int t4 = 0; t4 < 4; ++t4) {
                    int t = hh * 4 + t4, wp = 8 * t4 + 2 * j;
                    float b2a = __ldg(b2g + bb + u * 32 + wp);
                    float b2b = __ldg(b2g + bb + u * 32 + wp + 1);
                    int i0 = 2 * t4, i1 = i0 + 1;
                    accS[0][i0] = fmaf(c0, acc[t][0] + b2a, accS[0][i0]);
                    accS[0][i1] = fmaf(c0, acc[t][1] + b2b, accS[0][i1]);
                    accS[1][i0] = fmaf(c1, acc[t][2] + b2a, accS[1][i0]);
                    accS[1][i1] = fmaf(c1, acc[t][3] + b2b, accS[1][i1]);
                }
            }
        }

        __syncthreads();                               // all warps done with buf[c&1]
        if (c + 2 < 64) {
            const unsigned char* src = g_W2T + (size_t)(c + 2) * 34816;
            uint32_t dst = sb + ((c & 1) ? BUF1 : BUF0);
            #pragma unroll 1
            for (int off = tid * 16; off < 34816; off += 4096)
                cp16(dst + off, src + off);
        }
        CP_COMMIT();

        if (c == 31) {                                 // out0 complete (blocks A+D)
            float* op0 = outacc + (size_t)SR[e0] * 128;
            float* op1 = outacc + (size_t)SR[e1] * 128;
            #pragma unroll
            for (int i = 0; i < 8; ++i) {
                int wp = 8 * (i >> 1) + 2 * j + (i & 1);
                atomicAdd(op0 + wp, accS[0][i]);
                atomicAdd(op1 + wp, accS[1][i]);
                accS[0][i] = 0.f; accS[1][i] = 0.f;    // reuse as tB
            }
        }
    }
    CP_WAIT(0);

    // ---- final scatter: out1[w',i] = s1_i*tB[w'] + p0*vC_i[w'] ----
    {
        float sx0 = D1s[e0], sy0 = D1s[128+e0], sz0 = D1s[256+e0], pp0 = P0s[e0];
        float sx1 = D1s[e1], sy1 = D1s[128+e1], sz1 = D1s[256+e1], pp1 = P0s[e1];
        float* op0 = outacc + (size_t)SR[e0] * 128 + 32;
        float* op1 = outacc + (size_t)SR[e1] * 128 + 32;
        #pragma unroll
        for (int i = 0; i < 8; ++i) {
            int wp = 8 * (i >> 1) + 2 * j + (i & 1);
            atomicAdd(op0 + wp*3 + 0, fmaf(sx0, accS[0][i], pp0 * vC[0][0][i]));
            atomicAdd(op0 + wp*3 + 1, fmaf(sy0, accS[0][i], pp0 * vC[1][0][i]));
            atomicAdd(op0 + wp*3 + 2, fmaf(sz0, accS[0][i], pp0 * vC[2][0][i]));
            atomicAdd(op1 + wp*3 + 0, fmaf(sx1, accS[1][i], pp1 * vC[0][1][i]));
            atomicAdd(op1 + wp*3 + 1, fmaf(sy1, accS[1][i], pp1 * vC[1][1][i]));
            atomicAdd(op1 + wp*3 + 2, fmaf(sz1, accS[1][i], pp1 * vC[2][1][i]));
        }
    }
}

// ============================ tail kernels =================================
__global__ void k_zero(float* __restrict__ outp, int n_out, int N)
{
    int i = blockIdx.x * blockDim.x + threadIdx.x;
    int stride = gridDim.x * blockDim.x;
    for (int t = i; t < n_out; t += stride) outp[t] = 0.f;
    for (int t = i; t < N;     t += stride) g_cnt[t] = 0.f;
    for (int t = i; t < 96;    t += stride) g_stats[t] = 0.0;
}

__global__ __launch_bounds__(256)
void k_stats(float* __restrict__ outp, const float* __restrict__ node_attr, int N)
{
    __shared__ float sS[32], sS2[32], sV2[32];
    int tid = threadIdx.x;
    if (tid < 32) { sS[tid] = 0.f; sS2[tid] = 0.f; sV2[tid] = 0.f; }
    __syncthreads();
    int r = blockIdx.x * 32 + (tid >> 3);
    int j = tid & 7;
    if (r < N) {
        float inv = 1.0f / fmaxf(g_cnt[r], 1.0f);
        size_t base = (size_t)r * 128 + j * 16;
        float v[16];
        #pragma unroll
        for (int t = 0; t < 4; ++t) {
            float4 a = *reinterpret_cast<const float4*>(outp + base + t * 4);
            float4 b = *reinterpret_cast<const float4*>(node_attr + base + t * 4);
            v[t*4+0] = fmaf(a.x, inv, b.x);
            v[t*4+1] = fmaf(a.y, inv, b.y);
            v[t*4+2] = fmaf(a.z, inv, b.z);
            v[t*4+3] = fmaf(a.w, inv, b.w);
            *reinterpret_cast<float4*>(outp + base + t * 4) =
                make_float4(v[t*4+0], v[t*4+1], v[t*4+2], v[t*4+3]);
        }
        if (j < 2) {
            #pragma unroll
            for (int t = 0; t < 16; ++t) {
                int c = j * 16 + t;
                atomicAdd(&sS[c],  v[t]);
                atomicAdd(&sS2[c], v[t] * v[t]);
            }
        } else {
            #pragma unroll
            for (int t = 0; t < 16; ++t) {
                int c = j * 16 + t;
                atomicAdd(&sV2[(c - 32) / 3], v[t] * v[t]);
            }
        }
    }
    __syncthreads();
    if (tid < 32) {
        atomicAdd(&g_stats[tid],      (double)sS[tid]);
        atomicAdd(&g_stats[32 + tid], (double)sS2[tid]);
        atomicAdd(&g_stats[64 + tid], (double)sV2[tid]);
    }
}

__global__ void k_apply(float* __restrict__ outp,
                        const float* __restrict__ bnw,
                        const float* __restrict__ bnb,
                        int N, int total)
{
    __shared__ float pAll[128], qAll[128];
    int tid = threadIdx.x;
    if (tid < 128) {
        float p, q = 0.f;
        if (tid < 32) {
            double meanS = g_stats[tid] / N;
            double var   = g_stats[32 + tid] / N - meanS * meanS;
            p = rsqrtf((float)var + F_EPS) * bnw[tid];
            q = bnb[tid] - (float)meanS * p;
        } else {
            int u = (tid - 32) / 3;
            double mv = g_stats[64 + u] / (3.0 * N);
            p = rsqrtf((float)mv + F_EPS) * bnw[32 + u];
        }
        pAll[tid] = p; qAll[tid] = q;
    }
    __syncthreads();
    int stride = gridDim.x * blockDim.x;
    for (int i = blockIdx.x * blockDim.x + tid; i < total; i += stride) {
        int c = i & 127;
        outp[i] = fmaf(outp[i], pAll[c], qAll[c]);
    }
}

// ===========================================================================
extern "C" void kernel_launch(void* const* d_in, const int* in_sizes, int n_in,
                              void* d_out, int out_size)
{
    const float* node_attr  = (const float*)d_in[0];
    const int*   edge_index = (const int*)  d_in[1];
    const float* edge_attr  = (const float*)d_in[2];
    const float* edge_sh    = (const float*)d_in[3];
    const float* W1         = (const float*)d_in[4];
    const float* b1         = (const float*)d_in[5];
    const float* W2         = (const float*)d_in[6];
    const float* b2         = (const float*)d_in[7];
    const float* bnw        = (const float*)d_in[8];
    const float* bnb        = (const float*)d_in[9];
    float* outp = (float*)d_out;

    const int N = in_sizes[0] / 128;
    const int E = in_sizes[2] / 128;

    cudaFuncSetAttribute(k_main, cudaFuncAttributeMaxDynamicSharedMemorySize, SMEM_SZ);

    k_zero   <<<256, 256>>>(outp, out_size, N);
    k_prep_w1<<<64, 256>>>(W1);
    k_prep_w2<<<2048, 256>>>(W2);
    k_main   <<<(E + 127) / 128, 256, SMEM_SZ>>>(node_attr, edge_index, edge_attr,
                                                 edge_sh, b1, b2, outp, E);
    k_stats  <<<(N + 31) / 32, 256>>>(outp, node_attr, N);
    k_apply  <<<512, 256>>>(outp, bnw, bnb, N, out_size);
}

// round 9
// speedup vs baseline: 3.1445x; 1.1906x over previous
#include <cuda_runtime.h>
#include <cuda_fp16.h>
#include <cstdint>

// ============================ problem constants ============================
static constexpr float F_EPS = 1e-5f;
static constexpr float PN    = 0.125f;                        // 1/sqrt(2*32)
static constexpr float PIS3  = 0.125f * 0.57735026918962576f; // PN/sqrt(3)

// ============================ device scratch ===============================
static __device__ float  g_cnt[10240];
static __device__ double g_stats[96];
// Padded (272B-row) fp16 hi/lo weight images, cp.async-staged verbatim:
//  W1T: 128 rows(n) x 128(k): hi [0,34816) | lo [34816,69632)
static __device__ __align__(128) unsigned char g_W1T[69632];
//  W2T: 64 chunks; chunk = 64 rows(n) x 128(k): hi 17408 | lo 17408
static __device__ __align__(128) unsigned char g_W2T[64 * 34816];

// ============================ smem layout ==================================
static constexpr uint32_t HT   = 0;        // 34816: EA/H fp16 tile (272B rows)
static constexpr uint32_t XR   = 34816;    // 65536: X transposed [j][e] fp32
static constexpr uint32_t BUF0 = 100352;   // 3 ring slots, 34816 each
static constexpr uint32_t BUF1 = 135168;
static constexpr uint32_t BUF2 = 169984;
static constexpr uint32_t COEF = 204800;   // 640 f32 coefs + 128 srcs
static constexpr uint32_t SMEM_SZ = 207872;

// ============================ PTX helpers ==================================
__device__ __forceinline__ uint32_t smem_u32(const void* p) {
    uint32_t a;
    asm("{ .reg .u64 t; cvta.to.shared.u64 t, %1; cvt.u32.u64 %0, t; }" : "=r"(a) : "l"(p));
    return a;
}
__device__ __forceinline__ void ldsm_x4(uint32_t (&r)[4], uint32_t a) {
    asm volatile("ldmatrix.sync.aligned.m8n8.x4.shared.b16 {%0,%1,%2,%3}, [%4];"
        : "=r"(r[0]), "=r"(r[1]), "=r"(r[2]), "=r"(r[3]) : "r"(a));
}
__device__ __forceinline__ void mma_f16(float (&d)[4], const uint32_t (&a)[4],
                                        uint32_t b0, uint32_t b1) {
    asm volatile(
        "mma.sync.aligned.m16n8k16.row.col.f32.f16.f16.f32 "
        "{%0,%1,%2,%3}, {%4,%5,%6,%7}, {%8,%9}, {%0,%1,%2,%3};"
        : "+f"(d[0]), "+f"(d[1]), "+f"(d[2]), "+f"(d[3])
        : "r"(a[0]), "r"(a[1]), "r"(a[2]), "r"(a[3]), "r"(b0), "r"(b1));
}
__device__ __forceinline__ void cp16(uint32_t s, const void* g) {
    asm volatile("cp.async.cg.shared.global [%0], [%1], 16;" :: "r"(s), "l"(g));
}
#define CP_COMMIT() asm volatile("cp.async.commit_group;" ::: "memory")
#define CP_WAIT(n)  asm volatile("cp.async.wait_group %0;" :: "n"(n) : "memory")

// ldmatrix lane->address maps (272B row stride):
// A-operand x4 (m16k16): M0 rows g0-7 k0 | M1 rows g8-15 k0 | M2 g0-7 k8 | M3 g8-15 k8
__device__ __forceinline__ uint32_t ldsm_addr_A(uint32_t base, int row0, int lane) {
    return base + (uint32_t)(row0 + ((lane >> 3) & 1) * 8 + (lane & 7)) * 272u
                + (uint32_t)(lane >> 4) * 16u;
}
// B-operand x4 (2x k16n8): M0 n0-7 k0 | M1 n0-7 k8 | M2 n8-15 k0 | M3 n8-15 k8
__device__ __forceinline__ uint32_t ldsm_addr_B(uint32_t base, int n0, int lane) {
    return base + (uint32_t)(n0 + (lane >> 4) * 8 + (lane & 7)) * 272u
                + (uint32_t)((lane >> 3) & 1) * 16u;
}

__device__ __forceinline__ uint32_t pack_h2(float a, float b) {
    __half2 t = __floats2half2_rn(a, b);
    return *reinterpret_cast<uint32_t*>(&t);
}
__device__ __forceinline__ float f16_hi(float a) {
    return __half2float(__float2half_rn(a));
}

// ============================ prep kernels =================================
__global__ void k_prep_w1(const float* __restrict__ W1)
{
    int idx = blockIdx.x * blockDim.x + threadIdx.x;   // k*128 + n
    if (idx >= 128 * 128) return;
    int n = idx & 127, k = idx >> 7;
    float v  = W1[k * 128 + n];                        // B'[n][k] = W1[k][n]
    float hi = f16_hi(v);
    uint32_t off = (uint32_t)n * 272u + (uint32_t)k * 2u;
    *reinterpret_cast<__half*>(g_W1T + off)         = __float2half_rn(hi);
    *reinterpret_cast<__half*>(g_W1T + 34816 + off) = __float2half_rn(v - hi);
}

__global__ void k_prep_w2(const float* __restrict__ W2)
{
    int idx = blockIdx.x * blockDim.x + threadIdx.x;   // c*8192 + k*64 + n
    if (idx >= 64 * 128 * 64) return;
    int n = idx & 63, k = (idx >> 6) & 127, c = idx >> 13;
    int bt = c >> 4;
    int bb = (bt == 0) ? 0 : (bt == 1) ? 3072 : (bt == 2) ? 1024 : 2048;  // A,D,B,C
    int u  = 2 * (c & 15) + (n >> 5);
    int col = bb + u * 32 + (n & 31);
    float v  = W2[k * 4096 + col];                     // B'[n][k] = W2[k][col]
    float hi = f16_hi(v);
    unsigned char* base = g_W2T + (size_t)c * 34816;
    uint32_t off = (uint32_t)n * 272u + (uint32_t)k * 2u;
    *reinterpret_cast<__half*>(base + off)         = __float2half_rn(hi);
    *reinterpret_cast<__half*>(base + 17408 + off) = __float2half_rn(v - hi);
}

// ============================ main kernel ==================================
__global__ __launch_bounds__(256, 1)
void k_main(const float* __restrict__ node_attr,
            const int*   __restrict__ edge_index,
            const float* __restrict__ edge_attr,
            const float* __restrict__ edge_sh,
            const float* __restrict__ b1g,
            const float* __restrict__ b2g,
            float* __restrict__ outacc,
            int E)
{
    extern __shared__ unsigned char smem[];
    const uint32_t sb = smem_u32(smem);
    const int tid  = threadIdx.x;
    const int lane = tid & 31;
    const int w    = tid >> 5;
    const int ebase = blockIdx.x * 128;

    // ---- stage W1T (69632B = hi|lo) into BUF0/BUF1 via cp.async ----
    {
        #pragma unroll 1
        for (int off = tid * 16; off < 69632; off += 4096)
            cp16(sb + BUF0 + off, g_W1T + off);
        CP_COMMIT();
    }

    // ---- stage EA (fp16, padded), X (transposed fp32), per-edge coefs ----
    {
        int e = tid >> 1, h = tid & 1, eg = ebase + e;
        float* X   = (float*)(smem + XR);
        float* A0s = (float*)(smem + COEF);      // PN*sh0
        float* D1s = A0s + 128;                  // PIS3*sh1x | +128 y | +256 z
        float* P0s = A0s + 512;                  // PIS3*sh0
        int*   SR  = (int*)(smem + COEF + 2560);
        if (eg < E) {
            const float4* ea = (const float4*)(edge_attr + (size_t)eg * 128 + h * 64);
            #pragma unroll
            for (int q = 0; q < 16; ++q) {
                float4 v = __ldg(ea + q);
                int jc = h * 64 + q * 4;
                uint32_t off = (uint32_t)e * 272u + (uint32_t)jc * 2u;
                *(uint32_t*)(smem + HT + off)     = pack_h2(v.x, v.y);
                *(uint32_t*)(smem + HT + off + 4) = pack_h2(v.z, v.w);
            }
            int dst = __ldg(edge_index + E + eg);
            const float4* xr = (const float4*)(node_attr + (size_t)dst * 128 + h * 64);
            #pragma unroll
            for (int q = 0; q < 16; ++q) {
                float4 v = __ldg(xr + q);
                int jr = h * 64 + q * 4;
                X[(jr + 0) * 128 + e] = v.x;  X[(jr + 1) * 128 + e] = v.y;
                X[(jr + 2) * 128 + e] = v.z;  X[(jr + 3) * 128 + e] = v.w;
            }
            if (h == 0) {
                int src = __ldg(edge_index + eg);
                float4 shv = __ldg((const float4*)(edge_sh + (size_t)eg * 4));
                A0s[e] = PN * shv.x;
                D1s[e] = PIS3 * shv.y; D1s[128 + e] = PIS3 * shv.z; D1s[256 + e] = PIS3 * shv.w;
                P0s[e] = PIS3 * shv.x;
                SR[e]  = src;
                atomicAdd(&g_cnt[src], 1.0f);
            }
        } else {
            #pragma unroll
            for (int q = 0; q < 16; ++q) {
                int jc = h * 64 + q * 4;
                uint32_t off = (uint32_t)e * 272u + (uint32_t)jc * 2u;
                *(uint32_t*)(smem + HT + off)     = 0u;
                *(uint32_t*)(smem + HT + off + 4) = 0u;
                X[(jc + 0) * 128 + e] = 0.f;  X[(jc + 1) * 128 + e] = 0.f;
                X[(jc + 2) * 128 + e] = 0.f;  X[(jc + 3) * 128 + e] = 0.f;
            }
            if (h == 0) {
                A0s[e] = 0.f; D1s[e] = 0.f; D1s[128 + e] = 0.f; D1s[256 + e] = 0.f;
                P0s[e] = 0.f; SR[e] = 0;
            }
        }
    }
    CP_WAIT(0);
    __syncthreads();                                   // (#1)

    const int g = lane >> 2, j = lane & 3;
    const uint32_t aAddr = ldsm_addr_A(sb + HT, 16 * w, lane);

    // =========================== FC1 (fp16x2 HMMA) ==========================
    {
        float acc1[16][4];
        #pragma unroll
        for (int t = 0; t < 16; ++t)
            acc1[t][0] = acc1[t][1] = acc1[t][2] = acc1[t][3] = 0.f;
        #pragma unroll 2
        for (int k = 0; k < 8; ++k) {
            uint32_t A[4];
            ldsm_x4(A, aAddr + k * 32);
            #pragma unroll
            for (int p = 0; p < 8; ++p) {
                uint32_t Bh[4], Bl[4];
                ldsm_x4(Bh, ldsm_addr_B(sb + BUF0, 16 * p, lane) + k * 32);
                ldsm_x4(Bl, ldsm_addr_B(sb + BUF1, 16 * p, lane) + k * 32);
                mma_f16(acc1[2*p],   A, Bh[0], Bh[1]);
                mma_f16(acc1[2*p+1], A, Bh[2], Bh[3]);
                mma_f16(acc1[2*p],   A, Bl[0], Bl[1]);
                mma_f16(acc1[2*p+1], A, Bl[2], Bl[3]);
            }
        }
        // epilogue: h = relu(D + b1) -> fp16, write back into H tile (own rows)
        int r0 = 16 * w + g, r1 = r0 + 8;
        #pragma unroll
        for (int t = 0; t < 16; ++t) {
            int c0 = 8 * t + 2 * j;
            float b1a = __ldg(b1g + c0), b1b = __ldg(b1g + c0 + 1);
            float a0 = fmaxf(acc1[t][0] + b1a, 0.f), a1 = fmaxf(acc1[t][1] + b1b, 0.f);
            float a2 = fmaxf(acc1[t][2] + b1a, 0.f), a3 = fmaxf(acc1[t][3] + b1b, 0.f);
            uint32_t o0 = (uint32_t)r0 * 272u + (uint32_t)c0 * 2u;
            uint32_t o1 = (uint32_t)r1 * 272u + (uint32_t)c0 * 2u;
            *(uint32_t*)(smem + HT + o0) = pack_h2(a0, a1);
            *(uint32_t*)(smem + HT + o1) = pack_h2(a2, a3);
        }
    }
    __syncthreads();                                   // (#2) W1 buffers free, H final

    // prefetch FC2 chunks 0 and 1 into slots 0,1
    {
        #pragma unroll 1
        for (int off = tid * 16; off < 34816; off += 4096)
            cp16(sb + BUF0 + off, g_W2T + off);
        CP_COMMIT();
        #pragma unroll 1
        for (int off = tid * 16; off < 34816; off += 4096)
            cp16(sb + BUF1 + off, g_W2T + 34816 + off);
        CP_COMMIT();
    }

    // ---- A fragments register-resident for all 64 chunks ----
    uint32_t AF[8][4];
    #pragma unroll
    for (int k = 0; k < 8; ++k) ldsm_x4(AF[k], aAddr + k * 32);

    // =========================== FC2 + contraction ==========================
    const float* X   = (const float*)(smem + XR);
    const float* A0s = (const float*)(smem + COEF);
    const float* D1s = A0s + 128;
    const float* P0s = A0s + 512;
    const int*   SR  = (const int*)(smem + COEF + 2560);
    const int e0 = 16 * w + g, e1 = e0 + 8;

    float accS[2][8];                      // blocks A+D -> out0, then block B -> tB
    float vC[3][2][8];                     // block C
    #pragma unroll
    for (int i = 0; i < 8; ++i) { accS[0][i] = 0.f; accS[1][i] = 0.f; }

    #pragma unroll 1
    for (int c = 0; c < 64; ++c) {
        CP_WAIT(1);
        __syncthreads();       // chunk c visible everywhere; all warps done with c-1
        // prefetch c+2 into slot (c+2)%3 (== (c-1)%3, free since all passed barrier)
        if (c + 2 < 64) {
            const unsigned char* src = g_W2T + (size_t)(c + 2) * 34816;
            uint32_t dst = sb + BUF0 + (uint32_t)((c + 2) % 3) * 34816u;
            #pragma unroll 1
            for (int off = tid * 16; off < 34816; off += 4096)
                cp16(dst + off, src + off);
        }
        CP_COMMIT();

        const uint32_t bufB = sb + BUF0 + (uint32_t)(c % 3) * 34816u;
        float acc[8][4];
        #pragma unroll
        for (int t = 0; t < 8; ++t)
            acc[t][0] = acc[t][1] = acc[t][2] = acc[t][3] = 0.f;

        #pragma unroll
        for (int k = 0; k < 8; ++k) {
            uint32_t Bh[4][4], Bl[4][4];
            #pragma unroll
            for (int p = 0; p < 4; ++p) {
                ldsm_x4(Bh[p], ldsm_addr_B(bufB,         16 * p, lane) + k * 32);
                ldsm_x4(Bl[p], ldsm_addr_B(bufB + 17408, 16 * p, lane) + k * 32);
            }
            #pragma unroll
            for (int p = 0; p < 4; ++p) {
                mma_f16(acc[2*p],   AF[k], Bh[p][0], Bh[p][1]);
                mma_f16(acc[2*p+1], AF[k], Bh[p][2], Bh[p][3]);
            }
            #pragma unroll
            for (int p = 0; p < 4; ++p) {
                mma_f16(acc[2*p],   AF[k], Bl[p][0], Bl[p][1]);
                mma_f16(acc[2*p+1], AF[k], Bl[p][2], Bl[p][3]);
            }
        }

        // ---- contraction of this chunk's D fragments ----
        const int cw = c & 15, bt = c >> 4;
        const int bb = (bt == 0) ? 0 : (bt == 1) ? 3072 : (bt == 2) ? 1024 : 2048;
        if (c == 48) {
            #pragma unroll
            for (int i = 0; i < 8; ++i) {
                vC[0][0][i] = 0.f; vC[0][1][i] = 0.f;
                vC[1][0][i] = 0.f; vC[1][1][i] = 0.f;
                vC[2][0][i] = 0.f; vC[2][1][i] = 0.f;
            }
        }
        #pragma unroll
        for (int hh = 0; hh < 2; ++hh) {
            const int u = 2 * cw + hh;
            if (bt == 3) {
                float cx0 = X[(32+3*u)*128+e0], cy0 = X[(33+3*u)*128+e0], cz0 = X[(34+3*u)*128+e0];
                float cx1 = X[(32+3*u)*128+e1], cy1 = X[(33+3*u)*128+e1], cz1 = X[(34+3*u)*128+e1];
                #pragma unroll
                for (int t4 = 0; t4 < 4; ++t4) {
                    int t = hh * 4 + t4, wp = 8 * t4 + 2 * j;
                    float b2a = __ldg(b2g + bb + u * 32 + wp);
                    float b2b = __ldg(b2g + bb + u * 32 + wp + 1);
                    float y0 = acc[t][0] + b2a, y1 = acc[t][1] + b2b;
                    float y2 = acc[t][2] + b2a, y3 = acc[t][3] + b2b;
                    int i0 = 2 * t4, i1 = i0 + 1;
                    vC[0][0][i0] = fmaf(cx0, y0, vC[0][0][i0]); vC[0][0][i1] = fmaf(cx0, y1, vC[0][0][i1]);
                    vC[1][0][i0] = fmaf(cy0, y0, vC[1][0][i0]); vC[1][0][i1] = fmaf(cy0, y1, vC[1][0][i1]);
                    vC[2][0][i0] = fmaf(cz0, y0, vC[2][0][i0]); vC[2][0][i1] = fmaf(cz0, y1, vC[2][0][i1]);
                    vC[0][1][i0] = fmaf(cx1, y2, vC[0][1][i0]); vC[0][1][i1] = fmaf(cx1, y3, vC[0][1][i1]);
                    vC[1][1][i0] = fmaf(cy1, y2, vC[1][1][i0]); vC[1][1][i1] = fmaf(cy1, y3, vC[1][1][i1]);
                    vC[2][1][i0] = fmaf(cz1, y2, vC[2][1][i0]); vC[2][1][i1] = fmaf(cz1, y3, vC[2][1][i1]);
                }
            } else {
                float c0, c1;
                if (bt == 0) {
                    c0 = A0s[e0] * X[u*128+e0];
                    c1 = A0s[e1] * X[u*128+e1];
                } else if (bt == 1) {
                    c0 = D1s[e0]     * X[(32+3*u)*128+e0]
                       + D1s[128+e0] * X[(33+3*u)*128+e0]
                       + D1s[256+e0] * X[(34+3*u)*128+e0];
                    c1 = D1s[e1]     * X[(32+3*u)*128+e1]
                       + D1s[128+e1] * X[(33+3*u)*128+e1]
                       + D1s[256+e1] * X[(34+3*u)*128+e1];
                } else {
                    c0 = X[u*128+e0];
                    c1 = X[u*128+e1];
                }
                #pragma unroll
                for (int t4 = 0; t4 < 4; ++t4) {
                    int t = hh * 4 + t4, wp = 8 * t4 + 2 * j;
                    float b2a = __ldg(b2g + bb + u * 32 + wp);
                    float b2b = __ldg(b2g + bb + u * 32 + wp + 1);
                    int i0 = 2 * t4, i1 = i0 + 1;
                    accS[0][i0] = fmaf(c0, acc[t][0] + b2a, accS[0][i0]);
                    accS[0][i1] = fmaf(c0, acc[t][1] + b2b, accS[0][i1]);
                    accS[1][i0] = fmaf(c1, acc[t][2] + b2a, accS[1][i0]);
                    accS[1][i1] = fmaf(c1, acc[t][3] + b2b, accS[1][i1]);
                }
            }
        }

        if (c == 31) {                                 // out0 complete (blocks A+D)
            float* op0 = outacc + (size_t)SR[e0] * 128;
            float* op1 = outacc + (size_t)SR[e1] * 128;
            #pragma unroll
            for (int i = 0; i < 8; ++i) {
                int wp = 8 * (i >> 1) + 2 * j + (i & 1);
                atomicAdd(op0 + wp, accS[0][i]);
                atomicAdd(op1 + wp, accS[1][i]);
                accS[0][i] = 0.f; accS[1][i] = 0.f;    // reuse as tB
            }
        }
    }
    CP_WAIT(0);

    // ---- final scatter: out1[w',i] = s1_i*tB[w'] + p0*vC_i[w'] ----
    {
        float sx0 = D1s[e0], sy0 = D1s[128+e0], sz0 = D1s[256+e0], pp0 = P0s[e0];
        float sx1 = D1s[e1], sy1 = D1s[128+e1], sz1 = D1s[256+e1], pp1 = P0s[e1];
        float* op0 = outacc + (size_t)SR[e0] * 128 + 32;
        float* op1 = outacc + (size_t)SR[e1] * 128 + 32;
        #pragma unroll
        for (int i = 0; i < 8; ++i) {
            int wp = 8 * (i >> 1) + 2 * j + (i & 1);
            atomicAdd(op0 + wp*3 + 0, fmaf(sx0, accS[0][i], pp0 * vC[0][0][i]));
            atomicAdd(op0 + wp*3 + 1, fmaf(sy0, accS[0][i], pp0 * vC[1][0][i]));
            atomicAdd(op0 + wp*3 + 2, fmaf(sz0, accS[0][i], pp0 * vC[2][0][i]));
            atomicAdd(op1 + wp*3 + 0, fmaf(sx1, accS[1][i], pp1 * vC[0][1][i]));
            atomicAdd(op1 + wp*3 + 1, fmaf(sy1, accS[1][i], pp1 * vC[1][1][i]));
            atomicAdd(op1 + wp*3 + 2, fmaf(sz1, accS[1][i], pp1 * vC[2][1][i]));
        }
    }
}

// ============================ tail kernels =================================
__global__ void k_zero(float* __restrict__ outp, int n_out, int N)
{
    int i = blockIdx.x * blockDim.x + threadIdx.x;
    int stride = gridDim.x * blockDim.x;
    for (int t = i; t < n_out; t += stride) outp[t] = 0.f;
    for (int t = i; t < N;     t += stride) g_cnt[t] = 0.f;
    for (int t = i; t < 96;    t += stride) g_stats[t] = 0.0;
}

__global__ __launch_bounds__(256)
void k_stats(float* __restrict__ outp, const float* __restrict__ node_attr, int N)
{
    __shared__ float sS[32], sS2[32], sV2[32];
    int tid = threadIdx.x;
    if (tid < 32) { sS[tid] = 0.f; sS2[tid] = 0.f; sV2[tid] = 0.f; }
    __syncthreads();
    int r = blockIdx.x * 32 + (tid >> 3);
    int j = tid & 7;
    if (r < N) {
        float inv = 1.0f / fmaxf(g_cnt[r], 1.0f);
        size_t base = (size_t)r * 128 + j * 16;
        float v[16];
        #pragma unroll
        for (int t = 0; t < 4; ++t) {
            float4 a = *reinterpret_cast<const float4*>(outp + base + t * 4);
            float4 b = *reinterpret_cast<const float4*>(node_attr + base + t * 4);
            v[t*4+0] = fmaf(a.x, inv, b.x);
            v[t*4+1] = fmaf(a.y, inv, b.y);
            v[t*4+2] = fmaf(a.z, inv, b.z);
            v[t*4+3] = fmaf(a.w, inv, b.w);
            *reinterpret_cast<float4*>(outp + base + t * 4) =
                make_float4(v[t*4+0], v[t*4+1], v[t*4+2], v[t*4+3]);
        }
        if (j < 2) {
            #pragma unroll
            for (int t = 0; t < 16; ++t) {
                int c = j * 16 + t;
                atomicAdd(&sS[c],  v[t]);
                atomicAdd(&sS2[c], v[t] * v[t]);
            }
        } else {
            #pragma unroll
            for (int t = 0; t < 16; ++t) {
                int c = j * 16 + t;
                atomicAdd(&sV2[(c - 32) / 3], v[t] * v[t]);
            }
        }
    }
    __syncthreads();
    if (tid < 32) {
        atomicAdd(&g_stats[tid],      (double)sS[tid]);
        atomicAdd(&g_stats[32 + tid], (double)sS2[tid]);
        atomicAdd(&g_stats[64 + tid], (double)sV2[tid]);
    }
}

__global__ void k_apply(float* __restrict__ outp,
                        const float* __restrict__ bnw,
                        const float* __restrict__ bnb,
                        int N, int total)
{
    __shared__ float pAll[128], qAll[128];
    int tid = threadIdx.x;
    if (tid < 128) {
        float p, q = 0.f;
        if (tid < 32) {
            double meanS = g_stats[tid] / N;
            double var   = g_stats[32 + tid] / N - meanS * meanS;
            p = rsqrtf((float)var + F_EPS) * bnw[tid];
            q = bnb[tid] - (float)meanS * p;
        } else {
            int u = (tid - 32) / 3;
            double mv = g_stats[64 + u] / (3.0 * N);
            p = rsqrtf((float)mv + F_EPS) * bnw[32 + u];
        }
        pAll[tid] = p; qAll[tid] = q;
    }
    __syncthreads();
    int stride = gridDim.x * blockDim.x;
    for (int i = blockIdx.x * blockDim.x + tid; i < total; i += stride) {
        int c = i & 127;
        outp[i] = fmaf(outp[i], pAll[c], qAll[c]);
    }
}

// ===========================================================================
extern "C" void kernel_launch(void* const* d_in, const int* in_sizes, int n_in,
                              void* d_out, int out_size)
{
    const float* node_attr  = (const float*)d_in[0];
    const int*   edge_index = (const int*)  d_in[1];
    const float* edge_attr  = (const float*)d_in[2];
    const float* edge_sh    = (const float*)d_in[3];
    const float* W1         = (const float*)d_in[4];
    const float* b1         = (const float*)d_in[5];
    const float* W2         = (const float*)d_in[6];
    const float* b2         = (const float*)d_in[7];
    const float* bnw        = (const float*)d_in[8];
    const float* bnb        = (const float*)d_in[9];
    float* outp = (float*)d_out;

    const int N = in_sizes[0] / 128;
    const int E = in_sizes[2] / 128;

    cudaFuncSetAttribute(k_main, cudaFuncAttributeMaxDynamicSharedMemorySize, SMEM_SZ);

    k_zero   <<<256, 256>>>(outp, out_size, N);
    k_prep_w1<<<64, 256>>>(W1);
    k_prep_w2<<<2048, 256>>>(W2);
    k_main   <<<(E + 127) / 128, 256, SMEM_SZ>>>(node_attr, edge_index, edge_attr,
                                                 edge_sh, b1, b2, outp, E);
    k_stats  <<<(N + 31) / 32, 256>>>(outp, node_attr, N);
    k_apply  <<<512, 256>>>(outp, bnw, bnb, N, out_size);
}

// round 11
// speedup vs baseline: 4.3877x; 1.3954x over previous
#include <cuda_runtime.h>
#include <cuda_fp16.h>
#include <cstdint>

// ============================ problem constants ============================
static constexpr float F_EPS = 1e-5f;
static constexpr float PN    = 0.125f;                        // 1/sqrt(2*32)
static constexpr float PIS3  = 0.125f * 0.57735026918962576f; // PN/sqrt(3)

// ============================ device scratch ===============================
static __device__ float  g_cnt[10240];
static __device__ double g_stats[96];
// fp16 weight images with 272B-padded rows, cp.async-staged verbatim:
static __device__ __align__(128) unsigned char g_W1T[34816];        // 128 rows(n) x 128(k)
static __device__ __align__(128) unsigned char g_W2T[64 * 17408];   // chunk: 64 rows(n) x 128(k)

// ============================ smem layout ==================================
static constexpr uint32_t HT   = 0;        // 34816: EA/H fp16 tile (272B rows)
static constexpr uint32_t XR   = 34816;    // 65536: X transposed [j][e] fp32
static constexpr uint32_t BUFS = 100352;   // 3 ring slots x 17408 (W1 spans slots 0-1)
static constexpr uint32_t COEF = 152576;   // 640 f32 coefs + 128 srcs
static constexpr uint32_t SMEM_SZ = 155648;

// ============================ PTX helpers ==================================
__device__ __forceinline__ uint32_t smem_u32(const void* p) {
    uint32_t a;
    asm("{ .reg .u64 t; cvta.to.shared.u64 t, %1; cvt.u32.u64 %0, t; }" : "=r"(a) : "l"(p));
    return a;
}
__device__ __forceinline__ void ldsm_x4(uint32_t (&r)[4], uint32_t a) {
    asm volatile("ldmatrix.sync.aligned.m8n8.x4.shared.b16 {%0,%1,%2,%3}, [%4];"
        : "=r"(r[0]), "=r"(r[1]), "=r"(r[2]), "=r"(r[3]) : "r"(a));
}
__device__ __forceinline__ void mma_f16(float (&d)[4], const uint32_t (&a)[4],
                                        uint32_t b0, uint32_t b1) {
    asm volatile(
        "mma.sync.aligned.m16n8k16.row.col.f32.f16.f16.f32 "
        "{%0,%1,%2,%3}, {%4,%5,%6,%7}, {%8,%9}, {%0,%1,%2,%3};"
        : "+f"(d[0]), "+f"(d[1]), "+f"(d[2]), "+f"(d[3])
        : "r"(a[0]), "r"(a[1]), "r"(a[2]), "r"(a[3]), "r"(b0), "r"(b1));
}
__device__ __forceinline__ void cp16(uint32_t s, const void* g) {
    asm volatile("cp.async.cg.shared.global [%0], [%1], 16;" :: "r"(s), "l"(g));
}
#define CP_COMMIT() asm volatile("cp.async.commit_group;" ::: "memory")
#define CP_WAIT(n)  asm volatile("cp.async.wait_group %0;" :: "n"(n) : "memory")

// ldmatrix lane->address maps (272B row stride):
__device__ __forceinline__ uint32_t ldsm_addr_A(uint32_t base, int row0, int lane) {
    return base + (uint32_t)(row0 + ((lane >> 3) & 1) * 8 + (lane & 7)) * 272u
                + (uint32_t)(lane >> 4) * 16u;
}
__device__ __forceinline__ uint32_t ldsm_addr_B(uint32_t base, int n0, int lane) {
    return base + (uint32_t)(n0 + (lane >> 4) * 8 + (lane & 7)) * 272u
                + (uint32_t)((lane >> 3) & 1) * 16u;
}

__device__ __forceinline__ uint32_t pack_h2(float a, float b) {
    __half2 t = __floats2half2_rn(a, b);
    return *reinterpret_cast<uint32_t*>(&t);
}

// ============================ prep kernels =================================
__global__ void k_prep_w1(const float* __restrict__ W1)
{
    int idx = blockIdx.x * blockDim.x + threadIdx.x;   // k*128 + n
    if (idx >= 128 * 128) return;
    int n = idx & 127, k = idx >> 7;
    *reinterpret_cast<__half*>(g_W1T + (uint32_t)n * 272u + (uint32_t)k * 2u) =
        __float2half_rn(W1[k * 128 + n]);              // B'[n][k] = W1[k][n]
}

__global__ void k_prep_w2(const float* __restrict__ W2)
{
    int idx = blockIdx.x * blockDim.x + threadIdx.x;   // c*8192 + k*64 + n
    if (idx >= 64 * 128 * 64) return;
    int n = idx & 63, k = (idx >> 6) & 127, c = idx >> 13;
    int bt = c >> 4;
    int bb = (bt == 0) ? 0 : (bt == 1) ? 3072 : (bt == 2) ? 1024 : 2048;  // A,D,B,C
    int u  = 2 * (c & 15) + (n >> 5);
    int col = bb + u * 32 + (n & 31);
    *reinterpret_cast<__half*>(g_W2T + (size_t)c * 17408 +
                               (uint32_t)n * 272u + (uint32_t)k * 2u) =
        __float2half_rn(W2[k * 4096 + col]);           // B'[n][k] = W2[k][col]
}

// ============================ main kernel ==================================
__global__ __launch_bounds__(512, 1)
void k_main(const float* __restrict__ node_attr,
            const int*   __restrict__ edge_index,
            const float* __restrict__ edge_attr,
            const float* __restrict__ edge_sh,
            const float* __restrict__ b1g,
            const float* __restrict__ b2g,
            float* __restrict__ outacc,
            int E)
{
    extern __shared__ unsigned char smem[];
    const uint32_t sb = smem_u32(smem);
    const int tid  = threadIdx.x;
    const int lane = tid & 31;
    const int w    = tid >> 5;          // 0..15
    const int wq   = w & 7;             // m-tile (16 edges)
    const int half = w >> 3;            // n-half
    const int ebase = blockIdx.x * 128;

    // ---- stage W1T (34816B) into ring slots 0-1 via cp.async ----
    {
        #pragma unroll 1
        for (int off = tid * 16; off < 34816; off += 8192)
            cp16(sb + BUFS + off, g_W1T + off);
        CP_COMMIT();
    }

    // ---- stage EA (fp16, padded), X (transposed fp32), per-edge coefs ----
    {
        int e = tid >> 2, hx = tid & 3, eg = ebase + e;   // 4 threads/edge, 32 cols each
        float* X   = (float*)(smem + XR);
        float* A0s = (float*)(smem + COEF);      // PN*sh0
        float* D1s = A0s + 128;                  // PIS3*sh1x | +128 y | +256 z
        float* P0s = A0s + 512;                  // PIS3*sh0
        int*   SR  = (int*)(smem + COEF + 2560);
        if (eg < E) {
            const float4* ea = (const float4*)(edge_attr + (size_t)eg * 128 + hx * 32);
            #pragma unroll
            for (int q = 0; q < 8; ++q) {
                float4 v = __ldg(ea + q);
                int jc = hx * 32 + q * 4;
                uint32_t off = (uint32_t)e * 272u + (uint32_t)jc * 2u;
                *(uint32_t*)(smem + HT + off)     = pack_h2(v.x, v.y);
                *(uint32_t*)(smem + HT + off + 4) = pack_h2(v.z, v.w);
            }
            int dst = __ldg(edge_index + E + eg);
            const float4* xr = (const float4*)(node_attr + (size_t)dst * 128 + hx * 32);
            #pragma unroll
            for (int q = 0; q < 8; ++q) {
                float4 v = __ldg(xr + q);
                int jr = hx * 32 + q * 4;
                X[(jr + 0) * 128 + e] = v.x;  X[(jr + 1) * 128 + e] = v.y;
                X[(jr + 2) * 128 + e] = v.z;  X[(jr + 3) * 128 + e] = v.w;
            }
            if (hx == 0) {
                int src = __ldg(edge_index + eg);
                float4 shv = __ldg((const float4*)(edge_sh + (size_t)eg * 4));
                A0s[e] = PN * shv.x;
                D1s[e] = PIS3 * shv.y; D1s[128 + e] = PIS3 * shv.z; D1s[256 + e] = PIS3 * shv.w;
                P0s[e] = PIS3 * shv.x;
                SR[e]  = src;
                atomicAdd(&g_cnt[src], 1.0f);
            }
        } else {
            #pragma unroll
            for (int q = 0; q < 8; ++q) {
                int jc = hx * 32 + q * 4;
                uint32_t off = (uint32_t)e * 272u + (uint32_t)jc * 2u;
                *(uint32_t*)(smem + HT + off)     = 0u;
                *(uint32_t*)(smem + HT + off + 4) = 0u;
                X[(jc + 0) * 128 + e] = 0.f;  X[(jc + 1) * 128 + e] = 0.f;
                X[(jc + 2) * 128 + e] = 0.f;  X[(jc + 3) * 128 + e] = 0.f;
            }
            if (hx == 0) {
                A0s[e] = 0.f; D1s[e] = 0.f; D1s[128 + e] = 0.f; D1s[256 + e] = 0.f;
                P0s[e] = 0.f; SR[e] = 0;
            }
        }
    }
    CP_WAIT(0);
    __syncthreads();                                   // (#1) EA + W1 visible

    const int g = lane >> 2, j = lane & 3;
    const uint32_t aAddr = ldsm_addr_A(sb + HT, 16 * wq, lane);

    // =========================== FC1 (fp16 HMMA) ============================
    {
        // A fragments (EA) fully into regs first, so in-place h writeback is safe
        uint32_t AE[8][4];
        #pragma unroll
        for (int k = 0; k < 8; ++k) ldsm_x4(AE[k], aAddr + k * 32);

        float acc1[8][4];                              // warp's n-range: 64*half + 8t
        #pragma unroll
        for (int t = 0; t < 8; ++t)
            acc1[t][0] = acc1[t][1] = acc1[t][2] = acc1[t][3] = 0.f;
        #pragma unroll
        for (int k = 0; k < 8; ++k) {
            #pragma unroll
            for (int p = 0; p < 4; ++p) {
                uint32_t B[4];
                ldsm_x4(B, ldsm_addr_B(sb + BUFS, 64 * half + 16 * p, lane) + k * 32);
                mma_f16(acc1[2*p],   AE[k], B[0], B[1]);
                mma_f16(acc1[2*p+1], AE[k], B[2], B[3]);
            }
        }
        __syncthreads();                               // (#2) all EA reads done
        // epilogue: h = relu(D + b1) -> fp16, in-place into HT
        int r0 = 16 * wq + g, r1 = r0 + 8;
        #pragma unroll
        for (int t = 0; t < 8; ++t) {
            int c0 = 64 * half + 8 * t + 2 * j;
            float b1a = __ldg(b1g + c0), b1b = __ldg(b1g + c0 + 1);
            float a0 = fmaxf(acc1[t][0] + b1a, 0.f), a1 = fmaxf(acc1[t][1] + b1b, 0.f);
            float a2 = fmaxf(acc1[t][2] + b1a, 0.f), a3 = fmaxf(acc1[t][3] + b1b, 0.f);
            *(uint32_t*)(smem + HT + (uint32_t)r0 * 272u + (uint32_t)c0 * 2u) = pack_h2(a0, a1);
            *(uint32_t*)(smem + HT + (uint32_t)r1 * 272u + (uint32_t)c0 * 2u) = pack_h2(a2, a3);
        }
    }
    // prefetch FC2 chunks 0,1 (ring slots 0,1 — FC1 B reads finished at #2)
    {
        #pragma unroll 1
        for (int off = tid * 16; off < 17408; off += 8192)
            cp16(sb + BUFS + off, g_W2T + off);
        CP_COMMIT();
        #pragma unroll 1
        for (int off = tid * 16; off < 17408; off += 8192)
            cp16(sb + BUFS + 17408 + off, g_W2T + 17408 + off);
        CP_COMMIT();
    }
    __syncthreads();                                   // (#3) h final everywhere

    // ---- A fragments (h) register-resident for all 64 chunks ----
    uint32_t AF[8][4];
    #pragma unroll
    for (int k = 0; k < 8; ++k) ldsm_x4(AF[k], aAddr + k * 32);

    // =========================== FC2 + contraction ==========================
    const float* X   = (const float*)(smem + XR);
    const float* A0s = (const float*)(smem + COEF);
    const float* D1s = A0s + 128;
    const float* P0s = A0s + 512;
    const int*   SR  = (const int*)(smem + COEF + 2560);
    const int e0 = 16 * wq + g, e1 = e0 + 8;
    const int n0 = 32 * half;                          // warp's u = 2*cw + half

    float accS[2][8];                      // A+D -> out0, then B -> tB
    float vC[3][2][8];                     // block C
    #pragma unroll
    for (int i = 0; i < 8; ++i) { accS[0][i] = 0.f; accS[1][i] = 0.f; }

    #pragma unroll 1
    for (int c = 0; c < 64; ++c) {
        CP_WAIT(1);
        __syncthreads();     // chunk c ready; all warps done with slot (c+2)%3
        if (c + 2 < 64) {
            const unsigned char* src = g_W2T + (size_t)(c + 2) * 17408;
            uint32_t dst = sb + BUFS + (uint32_t)((c + 2) % 3) * 17408u;
            #pragma unroll 1
            for (int off = tid * 16; off < 17408; off += 8192)
                cp16(dst + off, src + off);
        }
        CP_COMMIT();

        const uint32_t bufB = sb + BUFS + (uint32_t)(c % 3) * 17408u;
        float acc[4][4];
        #pragma unroll
        for (int t = 0; t < 4; ++t)
            acc[t][0] = acc[t][1] = acc[t][2] = acc[t][3] = 0.f;

        #pragma unroll
        for (int k = 0; k < 8; ++k) {
            uint32_t B0[4], B1[4];
            ldsm_x4(B0, ldsm_addr_B(bufB, n0,      lane) + k * 32);
            ldsm_x4(B1, ldsm_addr_B(bufB, n0 + 16, lane) + k * 32);
            mma_f16(acc[0], AF[k], B0[0], B0[1]);
            mma_f16(acc[1], AF[k], B0[2], B0[3]);
            mma_f16(acc[2], AF[k], B1[0], B1[1]);
            mma_f16(acc[3], AF[k], B1[2], B1[3]);
        }

        // ---- contraction: this warp's u = 2*(c&15) + half ----
        const int cw = c & 15, bt = c >> 4;
        const int bb = (bt == 0) ? 0 : (bt == 1) ? 3072 : (bt == 2) ? 1024 : 2048;
        const int u  = 2 * cw + half;
        if (c == 48) {
            #pragma unroll
            for (int i = 0; i < 8; ++i) {
                vC[0][0][i] = 0.f; vC[0][1][i] = 0.f;
                vC[1][0][i] = 0.f; vC[1][1][i] = 0.f;
                vC[2][0][i] = 0.f; vC[2][1][i] = 0.f;
            }
        }
        if (bt == 3) {
            float cx0 = X[(32+3*u)*128+e0], cy0 = X[(33+3*u)*128+e0], cz0 = X[(34+3*u)*128+e0];
            float cx1 = X[(32+3*u)*128+e1], cy1 = X[(33+3*u)*128+e1], cz1 = X[(34+3*u)*128+e1];
            #pragma unroll
            for (int t4 = 0; t4 < 4; ++t4) {
                int wp = 8 * t4 + 2 * j;
                float b2a = __ldg(b2g + bb + u * 32 + wp);
                float b2b = __ldg(b2g + bb + u * 32 + wp + 1);
                float y0 = acc[t4][0] + b2a, y1 = acc[t4][1] + b2b;
                float y2 = acc[t4][2] + b2a, y3 = acc[t4][3] + b2b;
                int i0 = 2 * t4, i1 = i0 + 1;
                vC[0][0][i0] = fmaf(cx0, y0, vC[0][0][i0]); vC[0][0][i1] = fmaf(cx0, y1, vC[0][0][i1]);
                vC[1][0][i0] = fmaf(cy0, y0, vC[1][0][i0]); vC[1][0][i1] = fmaf(cy0, y1, vC[1][0][i1]);
                vC[2][0][i0] = fmaf(cz0, y0, vC[2][0][i0]); vC[2][0][i1] = fmaf(cz0, y1, vC[2][0][i1]);
                vC[0][1][i0] = fmaf(cx1, y2, vC[0][1][i0]); vC[0][1][i1] = fmaf(cx1, y3, vC[0][1][i1]);
                vC[1][1][i0] = fmaf(cy1, y2, vC[1][1][i0]); vC[1][1][i1] = fmaf(cy1, y3, vC[1][1][i1]);
                vC[2][1][i0] = fmaf(cz1, y2, vC[2][1][i0]); vC[2][1][i1] = fmaf(cz1, y3, vC[2][1][i1]);
            }
        } else {
            float c0, c1;
            if (bt == 0) {
                c0 = A0s[e0] * X[u*128+e0];
                c1 = A0s[e1] * X[u*128+e1];
            } else if (bt == 1) {
                c0 = D1s[e0]     * X[(32+3*u)*128+e0]
                   + D1s[128+e0] * X[(33+3*u)*128+e0]
                   + D1s[256+e0] * X[(34+3*u)*128+e0];
                c1 = D1s[e1]     * X[(32+3*u)*128+e1]
                   + D1s[128+e1] * X[(33+3*u)*128+e1]
                   + D1s[256+e1] * X[(34+3*u)*128+e1];
            } else {
                c0 = X[u*128+e0];
                c1 = X[u*128+e1];
            }
            #pragma unroll
            for (int t4 = 0; t4 < 4; ++t4) {
                int wp = 8 * t4 + 2 * j;
                float b2a = __ldg(b2g + bb + u * 32 + wp);
                float b2b = __ldg(b2g + bb + u * 32 + wp + 1);
                int i0 = 2 * t4, i1 = i0 + 1;
                accS[0][i0] = fmaf(c0, acc[t4][0] + b2a, accS[0][i0]);
                accS[0][i1] = fmaf(c0, acc[t4][1] + b2b, accS[0][i1]);
                accS[1][i0] = fmaf(c1, acc[t4][2] + b2a, accS[1][i0]);
                accS[1][i1] = fmaf(c1, acc[t4][3] + b2b, accS[1][i1]);
            }
        }

        if (c == 31) {                                 // out0 complete (A+D halves)
            float* op0 = outacc + (size_t)SR[e0] * 128;
            float* op1 = outacc + (size_t)SR[e1] * 128;
            #pragma unroll
            for (int i = 0; i < 8; ++i) {
                int wp = 8 * (i >> 1) + 2 * j + (i & 1);
                atomicAdd(op0 + wp, accS[0][i]);
                atomicAdd(op1 + wp, accS[1][i]);
                accS[0][i] = 0.f; accS[1][i] = 0.f;    // reuse as tB
            }
        }
    }
    CP_WAIT(0);

    // ---- final scatter: out1[w',i] += s1_i*tB[w'] + p0*vC_i[w'] ----
    {
        float sx0 = D1s[e0], sy0 = D1s[128+e0], sz0 = D1s[256+e0], pp0 = P0s[e0];
        float sx1 = D1s[e1], sy1 = D1s[128+e1], sz1 = D1s[256+e1], pp1 = P0s[e1];
        float* op0 = outacc + (size_t)SR[e0] * 128 + 32;
        float* op1 = outacc + (size_t)SR[e1] * 128 + 32;
        #pragma unroll
        for (int i = 0; i < 8; ++i) {
            int wp = 8 * (i >> 1) + 2 * j + (i & 1);
            atomicAdd(op0 + wp*3 + 0, fmaf(sx0, accS[0][i], pp0 * vC[0][0][i]));
            atomicAdd(op0 + wp*3 + 1, fmaf(sy0, accS[0][i], pp0 * vC[1][0][i]));
            atomicAdd(op0 + wp*3 + 2, fmaf(sz0, accS[0][i], pp0 * vC[2][0][i]));
            atomicAdd(op1 + wp*3 + 0, fmaf(sx1, accS[1][i], pp1 * vC[0][1][i]));
            atomicAdd(op1 + wp*3 + 1, fmaf(sy1, accS[1][i], pp1 * vC[1][1][i]));
            atomicAdd(op1 + wp*3 + 2, fmaf(sz1, accS[1][i], pp1 * vC[2][1][i]));
        }
    }
}

// ============================ tail kernels =================================
__global__ void k_zero(float* __restrict__ outp, int n_out, int N)
{
    int i = blockIdx.x * blockDim.x + threadIdx.x;
    int stride = gridDim.x * blockDim.x;
    for (int t = i; t < n_out; t += stride) outp[t] = 0.f;
    for (int t = i; t < N;     t += stride) g_cnt[t] = 0.f;
    for (int t = i; t < 96;    t += stride) g_stats[t] = 0.0;
}

__global__ __launch_bounds__(256)
void k_stats(float* __restrict__ outp, const float* __restrict__ node_attr, int N)
{
    __shared__ float sS[32], sS2[32], sV2[32];
    int tid = threadIdx.x;
    if (tid < 32) { sS[tid] = 0.f; sS2[tid] = 0.f; sV2[tid] = 0.f; }
    __syncthreads();
    int r = blockIdx.x * 32 + (tid >> 3);
    int j = tid & 7;
    if (r < N) {
        float inv = 1.0f / fmaxf(g_cnt[r], 1.0f);
        size_t base = (size_t)r * 128 + j * 16;
        float v[16];
        #pragma unroll
        for (int t = 0; t < 4; ++t) {
            float4 a = *reinterpret_cast<const float4*>(outp + base + t * 4);
            float4 b = *reinterpret_cast<const float4*>(node_attr + base + t * 4);
            v[t*4+0] = fmaf(a.x, inv, b.x);
            v[t*4+1] = fmaf(a.y, inv, b.y);
            v[t*4+2] = fmaf(a.z, inv, b.z);
            v[t*4+3] = fmaf(a.w, inv, b.w);
            *reinterpret_cast<float4*>(outp + base + t * 4) =
                make_float4(v[t*4+0], v[t*4+1], v[t*4+2], v[t*4+3]);
        }
        if (j < 2) {
            #pragma unroll
            for (int t = 0; t < 16; ++t) {
                int c = j * 16 + t;
                atomicAdd(&sS[c],  v[t]);
                atomicAdd(&sS2[c], v[t] * v[t]);
            }
        } else {
            #pragma unroll
            for (int t = 0; t < 16; ++t) {
                int c = j * 16 + t;
                atomicAdd(&sV2[(c - 32) / 3], v[t] * v[t]);
            }
        }
    }
    __syncthreads();
    if (tid < 32) {
        atomicAdd(&g_stats[tid],      (double)sS[tid]);
        atomicAdd(&g_stats[32 + tid], (double)sS2[tid]);
        atomicAdd(&g_stats[64 + tid], (double)sV2[tid]);
    }
}

__global__ void k_apply(float* __restrict__ outp,
                        const float* __restrict__ bnw,
                        const float* __restrict__ bnb,
                        int N, int total)
{
    __shared__ float pAll[128], qAll[128];
    int tid = threadIdx.x;
    if (tid < 128) {
        float p, q = 0.f;
        if (tid < 32) {
            double meanS = g_stats[tid] / N;
            double var   = g_stats[32 + tid] / N - meanS * meanS;
            p = rsqrtf((float)var + F_EPS) * bnw[tid];
            q = bnb[tid] - (float)meanS * p;
        } else {
            int u = (tid - 32) / 3;
            double mv = g_stats[64 + u] / (3.0 * N);
            p = rsqrtf((float)mv + F_EPS) * bnw[32 + u];
        }
        pAll[tid] = p; qAll[tid] = q;
    }
    __syncthreads();
    int stride = gridDim.x * blockDim.x;
    for (int i = blockIdx.x * blockDim.x + tid; i < total; i += stride) {
        int c = i & 127;
        outp[i] = fmaf(outp[i], pAll[c], qAll[c]);
    }
}

// ===========================================================================
extern "C" void kernel_launch(void* const* d_in, const int* in_sizes, int n_in,
                              void* d_out, int out_size)
{
    const float* node_attr  = (const float*)d_in[0];
    const int*   edge_index = (const int*)  d_in[1];
    const float* edge_attr  = (const float*)d_in[2];
    const float* edge_sh    = (const float*)d_in[3];
    const float* W1         = (const float*)d_in[4];
    const float* b1         = (const float*)d_in[5];
    const float* W2         = (const float*)d_in[6];
    const float* b2         = (const float*)d_in[7];
    const float* bnw        = (const float*)d_in[8];
    const float* bnb        = (const float*)d_in[9];
    float* outp = (float*)d_out;

    const int N = in_sizes[0] / 128;
    const int E = in_sizes[2] / 128;

    cudaFuncSetAttribute(k_main, cudaFuncAttributeMaxDynamicSharedMemorySize, SMEM_SZ);

    k_zero   <<<256, 256>>>(outp, out_size, N);
    k_prep_w1<<<64, 256>>>(W1);
    k_prep_w2<<<2048, 256>>>(W2);
    k_main   <<<(E + 127) / 128, 512, SMEM_SZ>>>(node_attr, edge_index, edge_attr,
                                                 edge_sh, b1, b2, outp, E);
    k_stats  <<<(N + 31) / 32, 256>>>(outp, node_attr, N);
    k_apply  <<<512, 256>>>(outp, bnw, bnb, N, out_size);
}

// round 14
// speedup vs baseline: 4.6932x; 1.0696x over previous
#include <cuda_runtime.h>
#include <cuda_fp16.h>
#include <cstdint>

// ============================ problem constants ============================
static constexpr float F_EPS = 1e-5f;
static constexpr float PN    = 0.125f;                        // 1/sqrt(2*32)
static constexpr float PIS3  = 0.125f * 0.57735026918962576f; // PN/sqrt(3)

// ============================ device scratch ===============================
static __device__ float  g_cnt[10240];
static __device__ double g_stats[96];
// fp16 weight images with 272B-padded rows, cp.async-staged verbatim:
static __device__ __align__(128) unsigned char g_W1T[34816];        // 128 rows(n) x 128(k)
static __device__ __align__(128) unsigned char g_W2T[64 * 17408];   // chunk: 64 rows(n) x 128(k)

// ============================ smem layout ==================================
static constexpr uint32_t HT   = 0;        // 34816: EA/H fp16 tile (272B rows)
static constexpr uint32_t XR   = 34816;    // 65536: X transposed [j][e] fp32
static constexpr uint32_t B2S  = 100352;   // 16384: b2 fp32
static constexpr uint32_t BUFS = 116736;   // 3 pair-slots x 34816
static constexpr uint32_t COEF = 221184;   // 640 f32 coefs + 128 srcs
static constexpr uint32_t SMEM_SZ = 224256;

// ============================ PTX helpers ==================================
__device__ __forceinline__ uint32_t smem_u32(const void* p) {
    uint32_t a;
    asm("{ .reg .u64 t; cvta.to.shared.u64 t, %1; cvt.u32.u64 %0, t; }" : "=r"(a) : "l"(p));
    return a;
}
__device__ __forceinline__ void ldsm_x4(uint32_t (&r)[4], uint32_t a) {
    asm volatile("ldmatrix.sync.aligned.m8n8.x4.shared.b16 {%0,%1,%2,%3}, [%4];"
        : "=r"(r[0]), "=r"(r[1]), "=r"(r[2]), "=r"(r[3]) : "r"(a));
}
__device__ __forceinline__ void mma_f16(float (&d)[4], const uint32_t (&a)[4],
                                        uint32_t b0, uint32_t b1) {
    asm volatile(
        "mma.sync.aligned.m16n8k16.row.col.f32.f16.f16.f32 "
        "{%0,%1,%2,%3}, {%4,%5,%6,%7}, {%8,%9}, {%0,%1,%2,%3};"
        : "+f"(d[0]), "+f"(d[1]), "+f"(d[2]), "+f"(d[3])
        : "r"(a[0]), "r"(a[1]), "r"(a[2]), "r"(a[3]), "r"(b0), "r"(b1));
}
__device__ __forceinline__ void cp16(uint32_t s, const void* g) {
    asm volatile("cp.async.cg.shared.global [%0], [%1], 16;" :: "r"(s), "l"(g));
}
#define CP_COMMIT() asm volatile("cp.async.commit_group;" ::: "memory")
#define CP_WAIT(n)  asm volatile("cp.async.wait_group %0;" :: "n"(n) : "memory")

// ldmatrix lane->address maps (272B row stride):
__device__ __forceinline__ uint32_t ldsm_addr_A(uint32_t base, int row0, int lane) {
    return base + (uint32_t)(row0 + ((lane >> 3) & 1) * 8 + (lane & 7)) * 272u
                + (uint32_t)(lane >> 4) * 16u;
}
__device__ __forceinline__ uint32_t ldsm_addr_B(uint32_t base, int n0, int lane) {
    return base + (uint32_t)(n0 + (lane >> 4) * 8 + (lane & 7)) * 272u
                + (uint32_t)((lane >> 3) & 1) * 16u;
}

__device__ __forceinline__ uint32_t pack_h2(float a, float b) {
    __half2 t = __floats2half2_rn(a, b);
    return *reinterpret_cast<uint32_t*>(&t);
}

// ============================ prep kernels =================================
__global__ void k_prep_w1(const float* __restrict__ W1)
{
    int idx = blockIdx.x * blockDim.x + threadIdx.x;   // k*128 + n
    if (idx >= 128 * 128) return;
    int n = idx & 127, k = idx >> 7;
    *reinterpret_cast<__half*>(g_W1T + (uint32_t)n * 272u + (uint32_t)k * 2u) =
        __float2half_rn(W1[k * 128 + n]);              // B'[n][k] = W1[k][n]
}

__global__ void k_prep_w2(const float* __restrict__ W2)
{
    int idx = blockIdx.x * blockDim.x + threadIdx.x;   // c*8192 + k*64 + n
    if (idx >= 64 * 128 * 64) return;
    int n = idx & 63, k = (idx >> 6) & 127, c = idx >> 13;
    int bt = c >> 4;
    int bb = (bt == 0) ? 0 : (bt == 1) ? 3072 : (bt == 2) ? 1024 : 2048;  // A,D,B,C
    int u  = 2 * (c & 15) + (n >> 5);
    int col = bb + u * 32 + (n & 31);
    *reinterpret_cast<__half*>(g_W2T + (size_t)c * 17408 +
                               (uint32_t)n * 272u + (uint32_t)k * 2u) =
        __float2half_rn(W2[k * 4096 + col]);           // B'[n][k] = W2[k][col]
}

// ============================ main kernel ==================================
__global__ __launch_bounds__(512, 1)
void k_main(const float* __restrict__ node_attr,
            const int*   __restrict__ edge_index,
            const float* __restrict__ edge_attr,
            const float* __restrict__ edge_sh,
            const float* __restrict__ b1g,
            const float* __restrict__ b2g,
            float* __restrict__ outacc,
            int E)
{
    extern __shared__ unsigned char smem[];
    const uint32_t sb = smem_u32(smem);
    const int tid  = threadIdx.x;
    const int lane = tid & 31;
    const int w    = tid >> 5;          // 0..15
    const int wq   = w & 7;             // m-tile (16 edges)
    const int half = w >> 3;            // n-half
    const int ebase = blockIdx.x * 128;

    // ---- stage W1T (34816B) into pair-slot 0, b2 (16KB) into B2S ----
    {
        #pragma unroll 1
        for (int off = tid * 16; off < 34816; off += 8192)
            cp16(sb + BUFS + off, g_W1T + off);
        #pragma unroll
        for (int q = 0; q < 2; ++q)
            cp16(sb + B2S + (tid + q * 512) * 16, b2g + (tid + q * 512) * 4);
        CP_COMMIT();
    }

    // ---- stage EA (fp16, padded), X (transposed fp32), per-edge coefs ----
    {
        int e = tid >> 2, hx = tid & 3, eg = ebase + e;   // 4 threads/edge, 32 cols each
        float* X   = (float*)(smem + XR);
        float* A0s = (float*)(smem + COEF);      // PN*sh0
        float* D1s = A0s + 128;                  // PIS3*sh1x | +128 y | +256 z
        float* P0s = A0s + 512;                  // PIS3*sh0
        int*   SR  = (int*)(smem + COEF + 2560);
        if (eg < E) {
            const float4* ea = (const float4*)(edge_attr + (size_t)eg * 128 + hx * 32);
            #pragma unroll
            for (int q = 0; q < 8; ++q) {
                float4 v = __ldg(ea + q);
                int jc = hx * 32 + q * 4;
                uint32_t off = (uint32_t)e * 272u + (uint32_t)jc * 2u;
                *(uint32_t*)(smem + HT + off)     = pack_h2(v.x, v.y);
                *(uint32_t*)(smem + HT + off + 4) = pack_h2(v.z, v.w);
            }
            int dst = __ldg(edge_index + E + eg);
            const float4* xr = (const float4*)(node_attr + (size_t)dst * 128 + hx * 32);
            #pragma unroll
            for (int q = 0; q < 8; ++q) {
                float4 v = __ldg(xr + q);
                int jr = hx * 32 + q * 4;
                X[(jr + 0) * 128 + e] = v.x;  X[(jr + 1) * 128 + e] = v.y;
                X[(jr + 2) * 128 + e] = v.z;  X[(jr + 3) * 128 + e] = v.w;
            }
            if (hx == 0) {
                int src = __ldg(edge_index + eg);
                float4 shv = __ldg((const float4*)(edge_sh + (size_t)eg * 4));
                A0s[e] = PN * shv.x;
                D1s[e] = PIS3 * shv.y; D1s[128 + e] = PIS3 * shv.z; D1s[256 + e] = PIS3 * shv.w;
                P0s[e] = PIS3 * shv.x;
                SR[e]  = src;
                atomicAdd(&g_cnt[src], 1.0f);
            }
        } else {
            #pragma unroll
            for (int q = 0; q < 8; ++q) {
                int jc = hx * 32 + q * 4;
                uint32_t off = (uint32_t)e * 272u + (uint32_t)jc * 2u;
                *(uint32_t*)(smem + HT + off)     = 0u;
                *(uint32_t*)(smem + HT + off + 4) = 0u;
                X[(jc + 0) * 128 + e] = 0.f;  X[(jc + 1) * 128 + e] = 0.f;
                X[(jc + 2) * 128 + e] = 0.f;  X[(jc + 3) * 128 + e] = 0.f;
            }
            if (hx == 0) {
                A0s[e] = 0.f; D1s[e] = 0.f; D1s[128 + e] = 0.f; D1s[256 + e] = 0.f;
                P0s[e] = 0.f; SR[e] = 0;
            }
        }
    }
    CP_WAIT(0);
    __syncthreads();                                   // (#1) EA + W1 + b2 visible

    const int g = lane >> 2, j = lane & 3;
    const uint32_t aAddr = ldsm_addr_A(sb + HT, 16 * wq, lane);
    const int n0 = 32 * half;
    // relative ldsm B addresses (slot-invariant)
    const uint32_t relB0 = ldsm_addr_B(0u, n0,      lane);
    const uint32_t relB1 = ldsm_addr_B(0u, n0 + 16, lane);

    // =========================== FC1 (fp16 HMMA) ============================
    {
        uint32_t AE[8][4];
        #pragma unroll
        for (int k = 0; k < 8; ++k) ldsm_x4(AE[k], aAddr + k * 32);

        float acc1[8][4];                              // warp's n-range: 64*half + 8t
        #pragma unroll
        for (int t = 0; t < 8; ++t)
            acc1[t][0] = acc1[t][1] = acc1[t][2] = acc1[t][3] = 0.f;
        #pragma unroll
        for (int k = 0; k < 8; ++k) {
            #pragma unroll
            for (int p = 0; p < 4; ++p) {
                uint32_t B[4];
                ldsm_x4(B, ldsm_addr_B(sb + BUFS, 64 * half + 16 * p, lane) + k * 32);
                mma_f16(acc1[2*p],   AE[k], B[0], B[1]);
                mma_f16(acc1[2*p+1], AE[k], B[2], B[3]);
            }
        }
        __syncthreads();                               // (#2) all EA reads done
        // epilogue: h = relu(D + b1) -> fp16, in-place into HT
        int r0 = 16 * wq + g, r1 = r0 + 8;
        #pragma unroll
        for (int t = 0; t < 8; ++t) {
            int c0 = 64 * half + 8 * t + 2 * j;
            float b1a = __ldg(b1g + c0), b1b = __ldg(b1g + c0 + 1);
            float a0 = fmaxf(acc1[t][0] + b1a, 0.f), a1 = fmaxf(acc1[t][1] + b1b, 0.f);
            float a2 = fmaxf(acc1[t][2] + b1a, 0.f), a3 = fmaxf(acc1[t][3] + b1b, 0.f);
            *(uint32_t*)(smem + HT + (uint32_t)r0 * 272u + (uint32_t)c0 * 2u) = pack_h2(a0, a1);
            *(uint32_t*)(smem + HT + (uint32_t)r1 * 272u + (uint32_t)c0 * 2u) = pack_h2(a2, a3);
        }
    }
    // prefetch FC2 pairs 0,1 (slots 0,1 — FC1 B reads finished before #2)
    {
        #pragma unroll 1
        for (int off = tid * 16; off < 34816; off += 8192)
            cp16(sb + BUFS + off, g_W2T + off);
        CP_COMMIT();
        #pragma unroll 1
        for (int off = tid * 16; off < 34816; off += 8192)
            cp16(sb + BUFS + 34816 + off, g_W2T + 34816 + off);
        CP_COMMIT();
    }
    __syncthreads();                                   // (#3) h final everywhere

    // ---- A fragments (h) register-resident for all 64 chunks ----
    uint32_t AF[8][4];
    #pragma unroll
    for (int k = 0; k < 8; ++k) ldsm_x4(AF[k], aAddr + k * 32);

    // =========================== FC2 + contraction ==========================
    const float* X   = (const float*)(smem + XR);
    const float* B2  = (const float*)(smem + B2S);
    const float* A0s = (const float*)(smem + COEF);
    const float* D1s = A0s + 128;
    const float* P0s = A0s + 512;
    const int*   SR  = (const int*)(smem + COEF + 2560);
    const int e0 = 16 * wq + g, e1 = e0 + 8;

    float accS[2][8];                      // A+D -> out0, then B -> tB
    float vC[3][2][8];                     // block C
    #pragma unroll
    for (int i = 0; i < 8; ++i) { accS[0][i] = 0.f; accS[1][i] = 0.f; }

    #pragma unroll 1
    for (int p = 0; p < 32; ++p) {                     // 32 steps x 2 chunks
        CP_WAIT(1);
        __syncthreads();     // pair p ready; all warps done with slot (p+2)%3
        if (p + 2 < 32) {
            const unsigned char* src = g_W2T + (size_t)(p + 2) * 34816;
            uint32_t dst = sb + BUFS + (uint32_t)((p + 2) % 3) * 34816u;
            #pragma unroll 1
            for (int off = tid * 16; off < 34816; off += 8192)
                cp16(dst + off, src + off);
        }
        CP_COMMIT();
        const uint32_t pairBase = sb + BUFS + (uint32_t)(p % 3) * 34816u;

        #pragma unroll
        for (int ih = 0; ih < 2; ++ih) {
            const int c  = 2 * p + ih;
            const int cw = c & 15, bt = c >> 4;
            const int bb = (bt == 0) ? 0 : (bt == 1) ? 3072 : (bt == 2) ? 1024 : 2048;
            const int u  = 2 * cw + half;
            const uint32_t bufB = pairBase + (uint32_t)ih * 17408u;

            // ---- hoisted coefficient + b2 loads (hide under MMAs) ----
            float b2r[8];
            #pragma unroll
            for (int t4 = 0; t4 < 4; ++t4) {
                b2r[2*t4]   = B2[bb + u * 32 + 8 * t4 + 2 * j];
                b2r[2*t4+1] = B2[bb + u * 32 + 8 * t4 + 2 * j + 1];
            }
            float c0 = 0.f, c1 = 0.f;
            float cx0, cy0, cz0, cx1, cy1, cz1;
            if (bt == 3) {
                cx0 = X[(32+3*u)*128+e0]; cy0 = X[(33+3*u)*128+e0]; cz0 = X[(34+3*u)*128+e0];
                cx1 = X[(32+3*u)*128+e1]; cy1 = X[(33+3*u)*128+e1]; cz1 = X[(34+3*u)*128+e1];
            } else if (bt == 0) {
                c0 = A0s[e0] * X[u*128+e0];
                c1 = A0s[e1] * X[u*128+e1];
            } else if (bt == 1) {
                c0 = D1s[e0]     * X[(32+3*u)*128+e0]
                   + D1s[128+e0] * X[(33+3*u)*128+e0]
                   + D1s[256+e0] * X[(34+3*u)*128+e0];
                c1 = D1s[e1]     * X[(32+3*u)*128+e1]
                   + D1s[128+e1] * X[(33+3*u)*128+e1]
                   + D1s[256+e1] * X[(34+3*u)*128+e1];
            } else {
                c0 = X[u*128+e0];
                c1 = X[u*128+e1];
            }

            float acc[4][4];
            #pragma unroll
            for (int t = 0; t < 4; ++t)
                acc[t][0] = acc[t][1] = acc[t][2] = acc[t][3] = 0.f;

            #pragma unroll
            for (int k = 0; k < 8; ++k) {
                uint32_t B0[4], B1[4];
                ldsm_x4(B0, bufB + relB0 + k * 32);
                ldsm_x4(B1, bufB + relB1 + k * 32);
                mma_f16(acc[0], AF[k], B0[0], B0[1]);
                mma_f16(acc[1], AF[k], B0[2], B0[3]);
                mma_f16(acc[2], AF[k], B1[0], B1[1]);
                mma_f16(acc[3], AF[k], B1[2], B1[3]);
            }

            // ---- register-only contraction ----
            if (c == 48) {
                #pragma unroll
                for (int i = 0; i < 8; ++i) {
                    vC[0][0][i] = 0.f; vC[0][1][i] = 0.f;
                    vC[1][0][i] = 0.f; vC[1][1][i] = 0.f;
                    vC[2][0][i] = 0.f; vC[2][1][i] = 0.f;
                }
            }
            if (bt == 3) {
                #pragma unroll
                for (int t4 = 0; t4 < 4; ++t4) {
                    float y0 = acc[t4][0] + b2r[2*t4], y1 = acc[t4][1] + b2r[2*t4+1];
                    float y2 = acc[t4][2] + b2r[2*t4], y3 = acc[t4][3] + b2r[2*t4+1];
                    int i0 = 2 * t4, i1 = i0 + 1;
                    vC[0][0][i0] = fmaf(cx0, y0, vC[0][0][i0]); vC[0][0][i1] = fmaf(cx0, y1, vC[0][0][i1]);
                    vC[1][0][i0] = fmaf(cy0, y0, vC[1][0][i0]); vC[1][0][i1] = fmaf(cy0, y1, vC[1][0][i1]);
                    vC[2][0][i0] = fmaf(cz0, y0, vC[2][0][i0]); vC[2][0][i1] = fmaf(cz0, y1, vC[2][0][i1]);
                    vC[0][1][i0] = fmaf(cx1, y2, vC[0][1][i0]); vC[0][1][i1] = fmaf(cx1, y3, vC[0][1][i1]);
                    vC[1][1][i0] = fmaf(cy1, y2, vC[1][1][i0]); vC[1][1][i1] = fmaf(cy1, y3, vC[1][1][i1]);
                    vC[2][1][i0] = fmaf(cz1, y2, vC[2][1][i0]); vC[2][1][i1] = fmaf(cz1, y3, vC[2][1][i1]);
                }
            } else {
                #pragma unroll
                for (int t4 = 0; t4 < 4; ++t4) {
                    int i0 = 2 * t4, i1 = i0 + 1;
                    accS[0][i0] = fmaf(c0, acc[t4][0] + b2r[2*t4],   accS[0][i0]);
                    accS[0][i1] = fmaf(c0, acc[t4][1] + b2r[2*t4+1], accS[0][i1]);
                    accS[1][i0] = fmaf(c1, acc[t4][2] + b2r[2*t4],   accS[1][i0]);
                    accS[1][i1] = fmaf(c1, acc[t4][3] + b2r[2*t4+1], accS[1][i1]);
                }
            }

            if (c == 31) {                             // out0 complete (A+D halves)
                float* op0 = outacc + (size_t)SR[e0] * 128;
                float* op1 = outacc + (size_t)SR[e1] * 128;
                #pragma unroll
                for (int i = 0; i < 8; ++i) {
                    int wp = 8 * (i >> 1) + 2 * j + (i & 1);
                    atomicAdd(op0 + wp, accS[0][i]);
                    atomicAdd(op1 + wp, accS[1][i]);
                    accS[0][i] = 0.f; accS[1][i] = 0.f;  // reuse as tB
                }
            }
        }
    }
    CP_WAIT(0);

    // ---- final scatter: out1[w',i] += s1_i*tB[w'] + p0*vC_i[w'] ----
    {
        float sx0 = D1s[e0], sy0 = D1s[128+e0], sz0 = D1s[256+e0], pp0 = P0s[e0];
        float sx1 = D1s[e1], sy1 = D1s[128+e1], sz1 = D1s[256+e1], pp1 = P0s[e1];
        float* op0 = outacc + (size_t)SR[e0] * 128 + 32;
        float* op1 = outacc + (size_t)SR[e1] * 128 + 32;
        #pragma unroll
        for (int i = 0; i < 8; ++i) {
            int wp = 8 * (i >> 1) + 2 * j + (i & 1);
            atomicAdd(op0 + wp*3 + 0, fmaf(sx0, accS[0][i], pp0 * vC[0][0][i]));
            atomicAdd(op0 + wp*3 + 1, fmaf(sy0, accS[0][i], pp0 * vC[1][0][i]));
            atomicAdd(op0 + wp*3 + 2, fmaf(sz0, accS[0][i], pp0 * vC[2][0][i]));
            atomicAdd(op1 + wp*3 + 0, fmaf(sx1, accS[1][i], pp1 * vC[0][1][i]));
            atomicAdd(op1 + wp*3 + 1, fmaf(sy1, accS[1][i], pp1 * vC[1][1][i]));
            atomicAdd(op1 + wp*3 + 2, fmaf(sz1, accS[1][i], pp1 * vC[2][1][i]));
        }
    }
}

// ============================ tail kernels =================================
__global__ void k_zero(float* __restrict__ outp, int n_out, int N)
{
    int i = blockIdx.x * blockDim.x + threadIdx.x;
    int stride = gridDim.x * blockDim.x;
    for (int t = i; t < n_out; t += stride) outp[t] = 0.f;
    for (int t = i; t < N;     t += stride) g_cnt[t] = 0.f;
    for (int t = i; t < 96;    t += stride) g_stats[t] = 0.0;
}

__global__ __launch_bounds__(256)
void k_stats(float* __restrict__ outp, const float* __restrict__ node_attr, int N)
{
    __shared__ float sS[32], sS2[32], sV2[32];
    int tid = threadIdx.x;
    if (tid < 32) { sS[tid] = 0.f; sS2[tid] = 0.f; sV2[tid] = 0.f; }
    __syncthreads();
    int r = blockIdx.x * 32 + (tid >> 3);
    int j = tid & 7;
    if (r < N) {
        float inv = 1.0f / fmaxf(g_cnt[r], 1.0f);
        size_t base = (size_t)r * 128 + j * 16;
        float v[16];
        #pragma unroll
        for (int t = 0; t < 4; ++t) {
            float4 a = *reinterpret_cast<const float4*>(outp + base + t * 4);
            float4 b = *reinterpret_cast<const float4*>(node_attr + base + t * 4);
            v[t*4+0] = fmaf(a.x, inv, b.x);
            v[t*4+1] = fmaf(a.y, inv, b.y);
            v[t*4+2] = fmaf(a.z, inv, b.z);
            v[t*4+3] = fmaf(a.w, inv, b.w);
            *reinterpret_cast<float4*>(outp + base + t * 4) =
                make_float4(v[t*4+0], v[t*4+1], v[t*4+2], v[t*4+3]);
        }
        if (j < 2) {
            #pragma unroll
            for (int t = 0; t < 16; ++t) {
                int c = j * 16 + t;
                atomicAdd(&sS[c],  v[t]);
                atomicAdd(&sS2[c], v[t] * v[t]);
            }
        } else {
            #pragma unroll
            for (int t = 0; t < 16; ++t) {
                int c = j * 16 + t;
                atomicAdd(&sV2[(c - 32) / 3], v[t] * v[t]);
            }
        }
    }
    __syncthreads();
    if (tid < 32) {
        atomicAdd(&g_stats[tid],      (double)sS[tid]);
        atomicAdd(&g_stats[32 + tid], (double)sS2[tid]);
        atomicAdd(&g_stats[64 + tid], (double)sV2[tid]);
    }
}

__global__ void k_apply(float* __restrict__ outp,
                        const float* __restrict__ bnw,
                        const float* __restrict__ bnb,
                        int N, int total)
{
    __shared__ float pAll[128], qAll[128];
    int tid = threadIdx.x;
    if (tid < 128) {
        float p, q = 0.f;
        if (tid < 32) {
            double meanS = g_stats[tid] / N;
            double var   = g_stats[32 + tid] / N - meanS * meanS;
            p = rsqrtf((float)var + F_EPS) * bnw[tid];
            q = bnb[tid] - (float)meanS * p;
        } else {
            int u = (tid - 32) / 3;
            double mv = g_stats[64 + u] / (3.0 * N);
            p = rsqrtf((float)mv + F_EPS) * bnw[32 + u];
        }
        pAll[tid] = p; qAll[tid] = q;
    }
    __syncthreads();
    int stride = gridDim.x * blockDim.x;
    for (int i = blockIdx.x * blockDim.x + tid; i < total; i += stride) {
        int c = i & 127;
        outp[i] = fmaf(outp[i], pAll[c], qAll[c]);
    }
}

// ===========================================================================
extern "C" void kernel_launch(void* const* d_in, const int* in_sizes, int n_in,
                              void* d_out, int out_size)
{
    const float* node_attr  = (const float*)d_in[0];
    const int*   edge_index = (const int*)  d_in[1];
    const float* edge_attr  = (const float*)d_in[2];
    const float* edge_sh    = (const float*)d_in[3];
    const float* W1         = (const float*)d_in[4];
    const float* b1         = (const float*)d_in[5];
    const float* W2         = (const float*)d_in[6];
    const float* b2         = (const float*)d_in[7];
    const float* bnw        = (const float*)d_in[8];
    const float* bnb        = (const float*)d_in[9];
    float* outp = (float*)d_out;

    const int N = in_sizes[0] / 128;
    const int E = in_sizes[2] / 128;

    cudaFuncSetAttribute(k_main, cudaFuncAttributeMaxDynamicSharedMemorySize, SMEM_SZ);

    k_zero   <<<256, 256>>>(outp, out_size, N);
    k_prep_w1<<<64, 256>>>(W1);
    k_prep_w2<<<2048, 256>>>(W2);
    k_main   <<<(E + 127) / 128, 512, SMEM_SZ>>>(node_attr, edge_index, edge_attr,
                                                 edge_sh, b1, b2, outp, E);
    k_stats  <<<(N + 31) / 32, 256>>>(outp, node_attr, N);
    k_apply  <<<512, 256>>>(outp, bnw, bnb, N, out_size);
}

// round 16
// speedup vs baseline: 4.6991x; 1.0012x over previous
#include <cuda_runtime.h>
#include <cuda_fp16.h>
#include <cstdint>

// ============================ problem constants ============================
static constexpr float F_EPS = 1e-5f;
static constexpr float PN    = 0.125f;                        // 1/sqrt(2*32)
static constexpr float PIS3  = 0.125f * 0.57735026918962576f; // PN/sqrt(3)

// ============================ device scratch ===============================
static __device__ float  g_cnt[10240];
static __device__ double g_stats[96];
// fp16 weight images with 272B-padded rows, cp.async-staged verbatim:
static __device__ __align__(128) unsigned char g_W1T[34816];        // 128 rows(n) x 128(k)
static __device__ __align__(128) unsigned char g_W2T[64 * 17408];   // chunk: 64 rows(n) x 128(k)

// ============================ smem layout (64-edge CTA, fits 2/SM) =========
static constexpr uint32_t HT   = 0;        // 17408: EA/H fp16 tile (272B rows)
static constexpr uint32_t XR   = 17408;    // 32768: X transposed [j][e] fp32 (stride 64)
static constexpr uint32_t BUFS = 50176;    // 3 chunk slots x 17408 (W1 spans slots 0-1)
static constexpr uint32_t COEF = 102400;   // 384 f32 coefs + 64 srcs
static constexpr uint32_t SMEM_SZ = 104448;

// ============================ PTX helpers ==================================
__device__ __forceinline__ uint32_t smem_u32(const void* p) {
    uint32_t a;
    asm("{ .reg .u64 t; cvta.to.shared.u64 t, %1; cvt.u32.u64 %0, t; }" : "=r"(a) : "l"(p));
    return a;
}
__device__ __forceinline__ void ldsm_x4(uint32_t (&r)[4], uint32_t a) {
    asm volatile("ldmatrix.sync.aligned.m8n8.x4.shared.b16 {%0,%1,%2,%3}, [%4];"
        : "=r"(r[0]), "=r"(r[1]), "=r"(r[2]), "=r"(r[3]) : "r"(a));
}
__device__ __forceinline__ void mma_f16(float (&d)[4], const uint32_t (&a)[4],
                                        uint32_t b0, uint32_t b1) {
    asm volatile(
        "mma.sync.aligned.m16n8k16.row.col.f32.f16.f16.f32 "
        "{%0,%1,%2,%3}, {%4,%5,%6,%7}, {%8,%9}, {%0,%1,%2,%3};"
        : "+f"(d[0]), "+f"(d[1]), "+f"(d[2]), "+f"(d[3])
        : "r"(a[0]), "r"(a[1]), "r"(a[2]), "r"(a[3]), "r"(b0), "r"(b1));
}
__device__ __forceinline__ void cp16(uint32_t s, const void* g) {
    asm volatile("cp.async.cg.shared.global [%0], [%1], 16;" :: "r"(s), "l"(g));
}
#define CP_COMMIT() asm volatile("cp.async.commit_group;" ::: "memory")
#define CP_WAIT(n)  asm volatile("cp.async.wait_group %0;" :: "n"(n) : "memory")

// ldmatrix lane->address maps (272B row stride):
__device__ __forceinline__ uint32_t ldsm_addr_A(uint32_t base, int row0, int lane) {
    return base + (uint32_t)(row0 + ((lane >> 3) & 1) * 8 + (lane & 7)) * 272u
                + (uint32_t)(lane >> 4) * 16u;
}
__device__ __forceinline__ uint32_t ldsm_addr_B(uint32_t base, int n0, int lane) {
    return base + (uint32_t)(n0 + (lane >> 4) * 8 + (lane & 7)) * 272u
                + (uint32_t)((lane >> 3) & 1) * 16u;
}

__device__ __forceinline__ uint32_t pack_h2(float a, float b) {
    __half2 t = __floats2half2_rn(a, b);
    return *reinterpret_cast<uint32_t*>(&t);
}

// ============================ prep kernels =================================
__global__ void k_prep_w1(const float* __restrict__ W1)
{
    int idx = blockIdx.x * blockDim.x + threadIdx.x;   // k*128 + n
    if (idx >= 128 * 128) return;
    int n = idx & 127, k = idx >> 7;
    *reinterpret_cast<__half*>(g_W1T + (uint32_t)n * 272u + (uint32_t)k * 2u) =
        __float2half_rn(W1[k * 128 + n]);              // B'[n][k] = W1[k][n]
}

__global__ void k_prep_w2(const float* __restrict__ W2)
{
    int idx = blockIdx.x * blockDim.x + threadIdx.x;   // c*8192 + k*64 + n
    if (idx >= 64 * 128 * 64) return;
    int n = idx & 63, k = (idx >> 6) & 127, c = idx >> 13;
    int bt = c >> 4;
    int bb = (bt == 0) ? 0 : (bt == 1) ? 3072 : (bt == 2) ? 1024 : 2048;  // A,D,B,C
    int u  = 2 * (c & 15) + (n >> 5);
    int col = bb + u * 32 + (n & 31);
    *reinterpret_cast<__half*>(g_W2T + (size_t)c * 17408 +
                               (uint32_t)n * 272u + (uint32_t)k * 2u) =
        __float2half_rn(W2[k * 4096 + col]);           // B'[n][k] = W2[k][col]
}

// ============================ main kernel ==================================
__global__ __launch_bounds__(256, 2)
void k_main(const float* __restrict__ node_attr,
            const int*   __restrict__ edge_index,
            const float* __restrict__ edge_attr,
            const float* __restrict__ edge_sh,
            const float* __restrict__ b1g,
            const float* __restrict__ b2g,
            float* __restrict__ outacc,
            int E)
{
    extern __shared__ unsigned char smem[];
    const uint32_t sb = smem_u32(smem);
    const int tid  = threadIdx.x;
    const int lane = tid & 31;
    const int w    = tid >> 5;          // 0..7
    const int wq   = w & 3;             // m-tile (16 edges)
    const int half = w >> 2;            // n-half
    const int ebase = blockIdx.x * 64;

    // ---- stage W1T (34816B) into ring slots 0-1 via cp.async ----
    {
        #pragma unroll 1
        for (int off = tid * 16; off < 34816; off += 4096)
            cp16(sb + BUFS + off, g_W1T + off);
        CP_COMMIT();
    }

    // ---- stage EA (fp16, padded), X (transposed fp32), per-edge coefs ----
    {
        int e = tid >> 2, hx = tid & 3, eg = ebase + e;   // 4 threads/edge
        float* X   = (float*)(smem + XR);
        float* A0s = (float*)(smem + COEF);      // PN*sh0
        float* D1s = A0s + 64;                   // PIS3*sh1x | +64 y | +128 z
        float* P0s = A0s + 256;                  // PIS3*sh0
        int*   SR  = (int*)(smem + COEF + 1280);
        if (eg < E) {
            const float4* ea = (const float4*)(edge_attr + (size_t)eg * 128 + hx * 32);
            #pragma unroll
            for (int q = 0; q < 8; ++q) {
                float4 v = __ldg(ea + q);
                int jc = hx * 32 + q * 4;
                uint32_t off = (uint32_t)e * 272u + (uint32_t)jc * 2u;
                *(uint32_t*)(smem + HT + off)     = pack_h2(v.x, v.y);
                *(uint32_t*)(smem + HT + off + 4) = pack_h2(v.z, v.w);
            }
            int dst = __ldg(edge_index + E + eg);
            const float4* xr = (const float4*)(node_attr + (size_t)dst * 128 + hx * 32);
            #pragma unroll
            for (int q = 0; q < 8; ++q) {
                float4 v = __ldg(xr + q);
                int jr = hx * 32 + q * 4;
                X[(jr + 0) * 64 + e] = v.x;  X[(jr + 1) * 64 + e] = v.y;
                X[(jr + 2) * 64 + e] = v.z;  X[(jr + 3) * 64 + e] = v.w;
            }
            if (hx == 0) {
                int src = __ldg(edge_index + eg);
                float4 shv = __ldg((const float4*)(edge_sh + (size_t)eg * 4));
                A0s[e] = PN * shv.x;
                D1s[e] = PIS3 * shv.y; D1s[64 + e] = PIS3 * shv.z; D1s[128 + e] = PIS3 * shv.w;
                P0s[e] = PIS3 * shv.x;
                SR[e]  = src;
                atomicAdd(&g_cnt[src], 1.0f);
            }
        } else {
            #pragma unroll
            for (int q = 0; q < 8; ++q) {
                int jc = hx * 32 + q * 4;
                uint32_t off = (uint32_t)e * 272u + (uint32_t)jc * 2u;
                *(uint32_t*)(smem + HT + off)     = 0u;
                *(uint32_t*)(smem + HT + off + 4) = 0u;
                X[(jc + 0) * 64 + e] = 0.f;  X[(jc + 1) * 64 + e] = 0.f;
                X[(jc + 2) * 64 + e] = 0.f;  X[(jc + 3) * 64 + e] = 0.f;
            }
            if (hx == 0) {
                A0s[e] = 0.f; D1s[e] = 0.f; D1s[64 + e] = 0.f; D1s[128 + e] = 0.f;
                P0s[e] = 0.f; SR[e] = 0;
            }
        }
    }
    CP_WAIT(0);
    __syncthreads();                                   // (#1) EA + W1 visible

    const int g = lane >> 2, j = lane & 3;
    const uint32_t aAddr = ldsm_addr_A(sb + HT, 16 * wq, lane);
    const int n0 = 32 * half;
    const uint32_t relB0 = ldsm_addr_B(0u, n0,      lane);   // slot-invariant
    const uint32_t relB1 = ldsm_addr_B(0u, n0 + 16, lane);

    // =========================== FC1 (fp16 HMMA) ============================
    {
        uint32_t AE[8][4];
        #pragma unroll
        for (int k = 0; k < 8; ++k) ldsm_x4(AE[k], aAddr + k * 32);

        float acc1[8][4];                              // warp's n-range: 64*half + 8t
        #pragma unroll
        for (int t = 0; t < 8; ++t)
            acc1[t][0] = acc1[t][1] = acc1[t][2] = acc1[t][3] = 0.f;
        #pragma unroll
        for (int k = 0; k < 8; ++k) {
            #pragma unroll
            for (int p = 0; p < 4; ++p) {
                uint32_t B[4];
                ldsm_x4(B, ldsm_addr_B(sb + BUFS, 64 * half + 16 * p, lane) + k * 32);
                mma_f16(acc1[2*p],   AE[k], B[0], B[1]);
                mma_f16(acc1[2*p+1], AE[k], B[2], B[3]);
            }
        }
        __syncthreads();                               // (#2) all EA + W1 reads done
        // epilogue: h = relu(D + b1) -> fp16, in-place into HT
        int r0 = 16 * wq + g, r1 = r0 + 8;
        #pragma unroll
        for (int t = 0; t < 8; ++t) {
            int c0 = 64 * half + 8 * t + 2 * j;
            float b1a = __ldg(b1g + c0), b1b = __ldg(b1g + c0 + 1);
            float a0 = fmaxf(acc1[t][0] + b1a, 0.f), a1 = fmaxf(acc1[t][1] + b1b, 0.f);
            float a2 = fmaxf(acc1[t][2] + b1a, 0.f), a3 = fmaxf(acc1[t][3] + b1b, 0.f);
            *(uint32_t*)(smem + HT + (uint32_t)r0 * 272u + (uint32_t)c0 * 2u) = pack_h2(a0, a1);
            *(uint32_t*)(smem + HT + (uint32_t)r1 * 272u + (uint32_t)c0 * 2u) = pack_h2(a2, a3);
        }
    }
    // prefetch FC2 chunks 0,1 into slots 0,1 (W1 reads finished at #2)
    {
        #pragma unroll 1
        for (int off = tid * 16; off < 17408; off += 4096)
            cp16(sb + BUFS + off, g_W2T + off);
        CP_COMMIT();
        #pragma unroll 1
        for (int off = tid * 16; off < 17408; off += 4096)
            cp16(sb + BUFS + 17408 + off, g_W2T + 17408 + off);
        CP_COMMIT();
    }
    __syncthreads();                                   // (#3) h final everywhere

    // ---- A fragments (h) register-resident for all 64 chunks ----
    uint32_t AF[8][4];
    #pragma unroll
    for (int k = 0; k < 8; ++k) ldsm_x4(AF[k], aAddr + k * 32);

    // =========================== FC2 + contraction ==========================
    const float* X   = (const float*)(smem + XR);
    const float* A0s = (const float*)(smem + COEF);
    const float* D1s = A0s + 64;
    const float* P0s = A0s + 256;
    const int*   SR  = (const int*)(smem + COEF + 1280);
    const int e0 = 16 * wq + g, e1 = e0 + 8;

    float accS[2][8];                      // A+D -> out0, then B -> tB
    float vC[3][2][8];                     // block C
    #pragma unroll
    for (int i = 0; i < 8; ++i) { accS[0][i] = 0.f; accS[1][i] = 0.f; }

    #pragma unroll 1
    for (int c = 0; c < 64; ++c) {
        CP_WAIT(1);
        __syncthreads();     // chunk c ready; all warps done with slot (c+2)%3
        if (c + 2 < 64) {
            const unsigned char* src = g_W2T + (size_t)(c + 2) * 17408;
            uint32_t dst = sb + BUFS + (uint32_t)((c + 2) % 3) * 17408u;
            #pragma unroll 1
            for (int off = tid * 16; off < 17408; off += 4096)
                cp16(dst + off, src + off);
        }
        CP_COMMIT();

        const int cw = c & 15, bt = c >> 4;
        const int bb = (bt == 0) ? 0 : (bt == 1) ? 3072 : (bt == 2) ? 1024 : 2048;
        const int u  = 2 * cw + half;
        const uint32_t bufB = sb + BUFS + (uint32_t)(c % 3) * 17408u;

        // ---- hoisted coefficient + b2 loads (hide under MMAs) ----
        const float* b2p = b2g + bb + u * 32 + 2 * j;
        float b2r[8];
        #pragma unroll
        for (int t4 = 0; t4 < 4; ++t4) {
            b2r[2*t4]   = __ldg(b2p + 8 * t4);
            b2r[2*t4+1] = __ldg(b2p + 8 * t4 + 1);
        }
        float c0 = 0.f, c1 = 0.f;
        float cx0, cy0, cz0, cx1, cy1, cz1;
        if (bt == 3) {
            cx0 = X[(32+3*u)*64+e0]; cy0 = X[(33+3*u)*64+e0]; cz0 = X[(34+3*u)*64+e0];
            cx1 = X[(32+3*u)*64+e1]; cy1 = X[(33+3*u)*64+e1]; cz1 = X[(34+3*u)*64+e1];
        } else if (bt == 0) {
            c0 = A0s[e0] * X[u*64+e0];
            c1 = A0s[e1] * X[u*64+e1];
        } else if (bt == 1) {
            c0 = D1s[e0]     * X[(32+3*u)*64+e0]
               + D1s[64+e0]  * X[(33+3*u)*64+e0]
               + D1s[128+e0] * X[(34+3*u)*64+e0];
            c1 = D1s[e1]     * X[(32+3*u)*64+e1]
               + D1s[64+e1]  * X[(33+3*u)*64+e1]
               + D1s[128+e1] * X[(34+3*u)*64+e1];
        } else {
            c0 = X[u*64+e0];
            c1 = X[u*64+e1];
        }

        float acc[4][4];
        #pragma unroll
        for (int t = 0; t < 4; ++t)
            acc[t][0] = acc[t][1] = acc[t][2] = acc[t][3] = 0.f;

        #pragma unroll
        for (int k = 0; k < 8; ++k) {
            uint32_t B0[4], B1[4];
            ldsm_x4(B0, bufB + relB0 + k * 32);
            ldsm_x4(B1, bufB + relB1 + k * 32);
            mma_f16(acc[0], AF[k], B0[0], B0[1]);
            mma_f16(acc[1], AF[k], B0[2], B0[3]);
            mma_f16(acc[2], AF[k], B1[0], B1[1]);
            mma_f16(acc[3], AF[k], B1[2], B1[3]);
        }

        // ---- register-only contraction ----
        if (c == 48) {
            #pragma unroll
            for (int i = 0; i < 8; ++i) {
                vC[0][0][i] = 0.f; vC[0][1][i] = 0.f;
                vC[1][0][i] = 0.f; vC[1][1][i] = 0.f;
                vC[2][0][i] = 0.f; vC[2][1][i] = 0.f;
            }
        }
        if (bt == 3) {
            #pragma unroll
            for (int t4 = 0; t4 < 4; ++t4) {
                float y0 = acc[t4][0] + b2r[2*t4], y1 = acc[t4][1] + b2r[2*t4+1];
                float y2 = acc[t4][2] + b2r[2*t4], y3 = acc[t4][3] + b2r[2*t4+1];
                int i0 = 2 * t4, i1 = i0 + 1;
                vC[0][0][i0] = fmaf(cx0, y0, vC[0][0][i0]); vC[0][0][i1] = fmaf(cx0, y1, vC[0][0][i1]);
                vC[1][0][i0] = fmaf(cy0, y0, vC[1][0][i0]); vC[1][0][i1] = fmaf(cy0, y1, vC[1][0][i1]);
                vC[2][0][i0] = fmaf(cz0, y0, vC[2][0][i0]); vC[2][0][i1] = fmaf(cz0, y1, vC[2][0][i1]);
                vC[0][1][i0] = fmaf(cx1, y2, vC[0][1][i0]); vC[0][1][i1] = fmaf(cx1, y3, vC[0][1][i1]);
                vC[1][1][i0] = fmaf(cy1, y2, vC[1][1][i0]); vC[1][1][i1] = fmaf(cy1, y3, vC[1][1][i1]);
                vC[2][1][i0] = fmaf(cz1, y2, vC[2][1][i0]); vC[2][1][i1] = fmaf(cz1, y3, vC[2][1][i1]);
            }
        } else {
            #pragma unroll
            for (int t4 = 0; t4 < 4; ++t4) {
                int i0 = 2 * t4, i1 = i0 + 1;
                accS[0][i0] = fmaf(c0, acc[t4][0] + b2r[2*t4],   accS[0][i0]);
                accS[0][i1] = fmaf(c0, acc[t4][1] + b2r[2*t4+1], accS[0][i1]);
                accS[1][i0] = fmaf(c1, acc[t4][2] + b2r[2*t4],   accS[1][i0]);
                accS[1][i1] = fmaf(c1, acc[t4][3] + b2r[2*t4+1], accS[1][i1]);
            }
        }

        if (c == 31) {                                 // out0 complete (A+D halves)
            float* op0 = outacc + (size_t)SR[e0] * 128;
            float* op1 = outacc + (size_t)SR[e1] * 128;
            #pragma unroll
            for (int i = 0; i < 8; ++i) {
                int wp = 8 * (i >> 1) + 2 * j + (i & 1);
                atomicAdd(op0 + wp, accS[0][i]);
                atomicAdd(op1 + wp, accS[1][i]);
                accS[0][i] = 0.f; accS[1][i] = 0.f;    // reuse as tB
            }
        }
    }
    CP_WAIT(0);

    // ---- final scatter: out1[w',i] += s1_i*tB[w'] + p0*vC_i[w'] ----
    {
        float sx0 = D1s[e0], sy0 = D1s[64+e0], sz0 = D1s[128+e0], pp0 = P0s[e0];
        float sx1 = D1s[e1], sy1 = D1s[64+e1], sz1 = D1s[128+e1], pp1 = P0s[e1];
        float* op0 = outacc + (size_t)SR[e0] * 128 + 32;
        float* op1 = outacc + (size_t)SR[e1] * 128 + 32;
        #pragma unroll
        for (int i = 0; i < 8; ++i) {
            int wp = 8 * (i >> 1) + 2 * j + (i & 1);
            atomicAdd(op0 + wp*3 + 0, fmaf(sx0, accS[0][i], pp0 * vC[0][0][i]));
            atomicAdd(op0 + wp*3 + 1, fmaf(sy0, accS[0][i], pp0 * vC[1][0][i]));
            atomicAdd(op0 + wp*3 + 2, fmaf(sz0, accS[0][i], pp0 * vC[2][0][i]));
            atomicAdd(op1 + wp*3 + 0, fmaf(sx1, accS[1][i], pp1 * vC[0][1][i]));
            atomicAdd(op1 + wp*3 + 1, fmaf(sy1, accS[1][i], pp1 * vC[1][1][i]));
            atomicAdd(op1 + wp*3 + 2, fmaf(sz1, accS[1][i], pp1 * vC[2][1][i]));
        }
    }
}

// ============================ tail kernels =================================
__global__ void k_zero(float* __restrict__ outp, int n_out, int N)
{
    int i = blockIdx.x * blockDim.x + threadIdx.x;
    int stride = gridDim.x * blockDim.x;
    for (int t = i; t < n_out; t += stride) outp[t] = 0.f;
    for (int t = i; t < N;     t += stride) g_cnt[t] = 0.f;
    for (int t = i; t < 96;    t += stride) g_stats[t] = 0.0;
}

__global__ __launch_bounds__(256)
void k_stats(float* __restrict__ outp, const float* __restrict__ node_attr, int N)
{
    __shared__ float sS[32], sS2[32], sV2[32];
    int tid = threadIdx.x;
    if (tid < 32) { sS[tid] = 0.f; sS2[tid] = 0.f; sV2[tid] = 0.f; }
    __syncthreads();
    int r = blockIdx.x * 32 + (tid >> 3);
    int j = tid & 7;
    if (r < N) {
        float inv = 1.0f / fmaxf(g_cnt[r], 1.0f);
        size_t base = (size_t)r * 128 + j * 16;
        float v[16];
        #pragma unroll
        for (int t = 0; t < 4; ++t) {
            float4 a = *reinterpret_cast<const float4*>(outp + base + t * 4);
            float4 b = *reinterpret_cast<const float4*>(node_attr + base + t * 4);
            v[t*4+0] = fmaf(a.x, inv, b.x);
            v[t*4+1] = fmaf(a.y, inv, b.y);
            v[t*4+2] = fmaf(a.z, inv, b.z);
            v[t*4+3] = fmaf(a.w, inv, b.w);
            *reinterpret_cast<float4*>(outp + base + t * 4) =
                make_float4(v[t*4+0], v[t*4+1], v[t*4+2], v[t*4+3]);
        }
        if (j < 2) {
            #pragma unroll
            for (int t = 0; t < 16; ++t) {
                int c = j * 16 + t;
                atomicAdd(&sS[c],  v[t]);
                atomicAdd(&sS2[c], v[t] * v[t]);
            }
        } else {
            #pragma unroll
            for (int t = 0; t < 16; ++t) {
                int c = j * 16 + t;
                atomicAdd(&sV2[(c - 32) / 3], v[t] * v[t]);
            }
        }
    }
    __syncthreads();
    if (tid < 32) {
        atomicAdd(&g_stats[tid],      (double)sS[tid]);
        atomicAdd(&g_stats[32 + tid], (double)sS2[tid]);
        atomicAdd(&g_stats[64 + tid], (double)sV2[tid]);
    }
}

__global__ void k_apply(float* __restrict__ outp,
                        const float* __restrict__ bnw,
                        const float* __restrict__ bnb,
                        int N, int total)
{
    __shared__ float pAll[128], qAll[128];
    int tid = threadIdx.x;
    if (tid < 128) {
        float p, q = 0.f;
        if (tid < 32) {
            double meanS = g_stats[tid] / N;
            double var   = g_stats[32 + tid] / N - meanS * meanS;
            p = rsqrtf((float)var + F_EPS) * bnw[tid];
            q = bnb[tid] - (float)meanS * p;
        } else {
            int u = (tid - 32) / 3;
            double mv = g_stats[64 + u] / (3.0 * N);
            p = rsqrtf((float)mv + F_EPS) * bnw[32 + u];
        }
        pAll[tid] = p; qAll[tid] = q;
    }
    __syncthreads();
    int stride = gridDim.x * blockDim.x;
    for (int i = blockIdx.x * blockDim.x + tid; i < total; i += stride) {
        int c = i & 127;
        outp[i] = fmaf(outp[i], pAll[c], qAll[c]);
    }
}

// ===========================================================================
extern "C" void kernel_launch(void* const* d_in, const int* in_sizes, int n_in,
                              void* d_out, int out_size)
{
    const float* node_attr  = (const float*)d_in[0];
    const int*   edge_index = (const int*)  d_in[1];
    const float* edge_attr  = (const float*)d_in[2];
    const float* edge_sh    = (const float*)d_in[3];
    const float* W1         = (const float*)d_in[4];
    const float* b1         = (const float*)d_in[5];
    const float* W2         = (const float*)d_in[6];
    const float* b2         = (const float*)d_in[7];
    const float* bnw        = (const float*)d_in[8];
    const float* bnb        = (const float*)d_in[9];
    float* outp = (float*)d_out;

    const int N = in_sizes[0] / 128;
    const int E = in_sizes[2] / 128;

    cudaFuncSetAttribute(k_main, cudaFuncAttributeMaxDynamicSharedMemorySize, SMEM_SZ);

    k_zero   <<<256, 256>>>(outp, out_size, N);
    k_prep_w1<<<64, 256>>>(W1);
    k_prep_w2<<<2048, 256>>>(W2);
    k_main   <<<(E + 63) / 64, 256, SMEM_SZ>>>(node_attr, edge_index, edge_attr,
                                               edge_sh, b1, b2, outp, E);
    k_stats  <<<(N + 31) / 32, 256>>>(outp, node_attr, N);
    k_apply  <<<512, 256>>>(outp, bnw, bnb, N, out_size);
}